// round 1
// baseline (speedup 1.0000x reference)
#include <cuda_runtime.h>

#define BB 4
#define SS 2048
#define DD 1024
#define HH 16
#define HD 64
#define SCALE 0.125f

// Scratch (allocation-free rule: __device__ globals)
__device__ float g_q[BB*HH*SS*HD];   // [B,H,S,hd]
__device__ float g_k[BB*HH*SS*HD];
__device__ float g_v[BB*HH*SS*HD];
__device__ float g_ctx[BB*SS*DD];    // [B,S,D]

// ---------------------------------------------------------------------------
// QKV GEMM: C[8192,3072] = x[8192,1024] @ w[1024,3072] + b; scatter into q/k/v
// Block tile 64x64, K-tile 16, 256 threads, 4x4 micro-tile.
// ---------------------------------------------------------------------------
__global__ __launch_bounds__(256) void qkv_gemm_kernel(
    const float* __restrict__ x, const float* __restrict__ w,
    const float* __restrict__ bias)
{
    const int K = 1024, N = 3072;
    __shared__ float As[16][68];   // transposed A tile [k][m]
    __shared__ float Bs[16][64];   // [k][n]

    int tid = threadIdx.x;
    int m0 = blockIdx.y * 64;
    int n0 = blockIdx.x * 64;

    int arow = tid >> 2;            // 0..63
    int ac4  = (tid & 3) * 4;       // 0,4,8,12
    int brow = tid >> 4;            // 0..15
    int bc4  = (tid & 15) * 4;      // 0..60
    int ty = tid >> 4, tx = tid & 15;

    const float* Aptr = x + (m0 + arow) * K + ac4;
    const float* Bptr = w + brow * N + n0 + bc4;

    float acc[4][4];
#pragma unroll
    for (int i = 0; i < 4; i++)
#pragma unroll
        for (int j = 0; j < 4; j++) acc[i][j] = 0.f;

    for (int k0 = 0; k0 < K; k0 += 16) {
        float4 av = *(const float4*)(Aptr); Aptr += 16;
        float4 bv = *(const float4*)(Bptr); Bptr += 16 * N;
        As[ac4+0][arow] = av.x; As[ac4+1][arow] = av.y;
        As[ac4+2][arow] = av.z; As[ac4+3][arow] = av.w;
        *(float4*)&Bs[brow][bc4] = bv;
        __syncthreads();
#pragma unroll
        for (int k = 0; k < 16; k++) {
            float4 a = *(const float4*)&As[k][ty*4];
            float4 b = *(const float4*)&Bs[k][tx*4];
            acc[0][0] += a.x*b.x; acc[0][1] += a.x*b.y; acc[0][2] += a.x*b.z; acc[0][3] += a.x*b.w;
            acc[1][0] += a.y*b.x; acc[1][1] += a.y*b.y; acc[1][2] += a.y*b.z; acc[1][3] += a.y*b.w;
            acc[2][0] += a.z*b.x; acc[2][1] += a.z*b.y; acc[2][2] += a.z*b.z; acc[2][3] += a.z*b.w;
            acc[3][0] += a.w*b.x; acc[3][1] += a.w*b.y; acc[3][2] += a.w*b.z; acc[3][3] += a.w*b.w;
        }
        __syncthreads();
    }

    // Epilogue: scatter to q/k/v in [B,H,S,hd]; col = three*1024 + h*64 + dd
#pragma unroll
    for (int ii = 0; ii < 4; ii++) {
        int m = m0 + ty*4 + ii;
        int b = m >> 11;            // /2048
        int s = m & 2047;
#pragma unroll
        for (int jj = 0; jj < 4; jj++) {
            int n = n0 + tx*4 + jj;
            float c = acc[ii][jj] + bias[n];
            int three = n >> 10;
            int rem   = n & 1023;
            int h  = rem >> 6;
            int dd = rem & 63;
            int idx = ((b*HH + h)*SS + s)*HD + dd;
            if (three == 0)      g_q[idx] = c;
            else if (three == 1) g_k[idx] = c;
            else                 g_v[idx] = c;
        }
    }
}

// ---------------------------------------------------------------------------
// Flash attention (fp32): grid (S/64, B*H). BQ=64 queries, BKV=32 keys/tile.
// 256 threads. Online softmax. ~46KB static smem.
// ---------------------------------------------------------------------------
__global__ __launch_bounds__(256) void attn_kernel()
{
    __shared__ float Qt[64][68];    // Q^T [d][i], pre-scaled
    __shared__ float Kt[64][36];    // K^T [d][j]
    __shared__ float Vs[32][64];    // [k][d]
    __shared__ float St[32][68];    // scores/probs transposed [j][i]
    __shared__ float m_s[64], l_s[64], alpha_s[64];
    __shared__ float pmax[4][64], psum[4][64];

    int tid = threadIdx.x;
    int bh  = blockIdx.y;
    int q0  = blockIdx.x * 64;

    const float* Qg = g_q + (bh*SS + q0)*HD;
    const float* Kg = g_k + bh*SS*HD;
    const float* Vg = g_v + bh*SS*HD;

    // Load Q tile transposed, scaled: 64x64
    {
        int r = tid >> 2;
#pragma unroll
        for (int q = 0; q < 4; q++) {
            int c = ((tid & 3) * 4 + q) * 4;
            float4 v = *(const float4*)(Qg + r*HD + c);
            Qt[c+0][r] = v.x*SCALE; Qt[c+1][r] = v.y*SCALE;
            Qt[c+2][r] = v.z*SCALE; Qt[c+3][r] = v.w*SCALE;
        }
    }
    if (tid < 64) { m_s[tid] = -1e30f; l_s[tid] = 0.f; }

    int ty = tid >> 4, tx = tid & 15;     // compute mapping
    int si = tid & 63, wj = tid >> 6;     // softmax mapping: query si, worker wj

    float oacc[4][4];
#pragma unroll
    for (int i = 0; i < 4; i++)
#pragma unroll
        for (int j = 0; j < 4; j++) oacc[i][j] = 0.f;

    for (int kv0 = 0; kv0 < SS; kv0 += 32) {
        // Load K (transposed) and V tiles: 32 rows x 64 cols each
        {
            int r = tid >> 3;                 // 0..31
#pragma unroll
            for (int q = 0; q < 2; q++) {
                int c = (tid & 7) * 8 + q * 4;
                float4 kv = *(const float4*)(Kg + (kv0 + r)*HD + c);
                Kt[c+0][r] = kv.x; Kt[c+1][r] = kv.y;
                Kt[c+2][r] = kv.z; Kt[c+3][r] = kv.w;
                float4 vv = *(const float4*)(Vg + (kv0 + r)*HD + c);
                *(float4*)&Vs[r][c] = vv;
            }
        }
        __syncthreads();

        // Scores: S[i][j] = sum_d Qt[d][i]*Kt[d][j]; i=ty*4.., j=tx*2..
        {
            float sacc[4][2];
#pragma unroll
            for (int i = 0; i < 4; i++) { sacc[i][0] = 0.f; sacc[i][1] = 0.f; }
#pragma unroll 8
            for (int d = 0; d < 64; d++) {
                float4 a = *(const float4*)&Qt[d][ty*4];
                float2 b = *(const float2*)&Kt[d][tx*2];
                sacc[0][0] += a.x*b.x; sacc[0][1] += a.x*b.y;
                sacc[1][0] += a.y*b.x; sacc[1][1] += a.y*b.y;
                sacc[2][0] += a.z*b.x; sacc[2][1] += a.z*b.y;
                sacc[3][0] += a.w*b.x; sacc[3][1] += a.w*b.y;
            }
#pragma unroll
            for (int ii = 0; ii < 4; ii++) {
                St[tx*2+0][ty*4+ii] = sacc[ii][0];
                St[tx*2+1][ty*4+ii] = sacc[ii][1];
            }
        }
        __syncthreads();

        // Online softmax over rows (queries). 4 workers x 8 keys each.
        float mold = m_s[si];
        float lmax = -1e30f;
#pragma unroll
        for (int j = wj*8; j < wj*8 + 8; j++) lmax = fmaxf(lmax, St[j][si]);
        pmax[wj][si] = lmax;
        __syncthreads();

        float mnew = fmaxf(mold,
                     fmaxf(fmaxf(pmax[0][si], pmax[1][si]),
                           fmaxf(pmax[2][si], pmax[3][si])));
        float lsum = 0.f;
#pragma unroll
        for (int j = wj*8; j < wj*8 + 8; j++) {
            float p = __expf(St[j][si] - mnew);
            St[j][si] = p;
            lsum += p;
        }
        psum[wj][si] = lsum;
        __syncthreads();

        if (wj == 0) {
            float rs = psum[0][si] + psum[1][si] + psum[2][si] + psum[3][si];
            float alpha = __expf(mold - mnew);
            alpha_s[si] = alpha;
            l_s[si] = l_s[si] * alpha + rs;
            m_s[si] = mnew;
        }
        __syncthreads();

        // Rescale O, then O += P @ V  (i=ty*4.., d=tx*4..)
        {
            float a0 = alpha_s[ty*4+0], a1 = alpha_s[ty*4+1];
            float a2 = alpha_s[ty*4+2], a3 = alpha_s[ty*4+3];
#pragma unroll
            for (int j = 0; j < 4; j++) {
                oacc[0][j] *= a0; oacc[1][j] *= a1;
                oacc[2][j] *= a2; oacc[3][j] *= a3;
            }
#pragma unroll 8
            for (int k = 0; k < 32; k++) {
                float4 a = *(const float4*)&St[k][ty*4];
                float4 b = *(const float4*)&Vs[k][tx*4];
                oacc[0][0] += a.x*b.x; oacc[0][1] += a.x*b.y; oacc[0][2] += a.x*b.z; oacc[0][3] += a.x*b.w;
                oacc[1][0] += a.y*b.x; oacc[1][1] += a.y*b.y; oacc[1][2] += a.y*b.z; oacc[1][3] += a.y*b.w;
                oacc[2][0] += a.z*b.x; oacc[2][1] += a.z*b.y; oacc[2][2] += a.z*b.z; oacc[2][3] += a.z*b.w;
                oacc[3][0] += a.w*b.x; oacc[3][1] += a.w*b.y; oacc[3][2] += a.w*b.z; oacc[3][3] += a.w*b.w;
            }
        }
        __syncthreads();
    }

    // Write context: ctx[b, s, h*64+dd]
    int b = bh >> 4, h = bh & 15;
#pragma unroll
    for (int ii = 0; ii < 4; ii++) {
        int srow = q0 + ty*4 + ii;
        float inv = 1.0f / l_s[ty*4+ii];
        float4 o;
        o.x = oacc[ii][0]*inv; o.y = oacc[ii][1]*inv;
        o.z = oacc[ii][2]*inv; o.w = oacc[ii][3]*inv;
        *(float4*)(g_ctx + (b*SS + srow)*DD + h*HD + tx*4) = o;
    }
}

// ---------------------------------------------------------------------------
// Proj GEMM: out[8192,1024] = ctx[8192,1024] @ w_proj[1024,1024] + b_proj
// ---------------------------------------------------------------------------
__global__ __launch_bounds__(256) void proj_gemm_kernel(
    const float* __restrict__ w, const float* __restrict__ bias,
    float* __restrict__ out)
{
    const int K = 1024, N = 1024;
    __shared__ float As[16][68];
    __shared__ float Bs[16][64];

    int tid = threadIdx.x;
    int m0 = blockIdx.y * 64;
    int n0 = blockIdx.x * 64;

    int arow = tid >> 2;
    int ac4  = (tid & 3) * 4;
    int brow = tid >> 4;
    int bc4  = (tid & 15) * 4;
    int ty = tid >> 4, tx = tid & 15;

    const float* Aptr = g_ctx + (m0 + arow) * K + ac4;
    const float* Bptr = w + brow * N + n0 + bc4;

    float acc[4][4];
#pragma unroll
    for (int i = 0; i < 4; i++)
#pragma unroll
        for (int j = 0; j < 4; j++) acc[i][j] = 0.f;

    for (int k0 = 0; k0 < K; k0 += 16) {
        float4 av = *(const float4*)(Aptr); Aptr += 16;
        float4 bv = *(const float4*)(Bptr); Bptr += 16 * N;
        As[ac4+0][arow] = av.x; As[ac4+1][arow] = av.y;
        As[ac4+2][arow] = av.z; As[ac4+3][arow] = av.w;
        *(float4*)&Bs[brow][bc4] = bv;
        __syncthreads();
#pragma unroll
        for (int k = 0; k < 16; k++) {
            float4 a = *(const float4*)&As[k][ty*4];
            float4 b = *(const float4*)&Bs[k][tx*4];
            acc[0][0] += a.x*b.x; acc[0][1] += a.x*b.y; acc[0][2] += a.x*b.z; acc[0][3] += a.x*b.w;
            acc[1][0] += a.y*b.x; acc[1][1] += a.y*b.y; acc[1][2] += a.y*b.z; acc[1][3] += a.y*b.w;
            acc[2][0] += a.z*b.x; acc[2][1] += a.z*b.y; acc[2][2] += a.z*b.z; acc[2][3] += a.z*b.w;
            acc[3][0] += a.w*b.x; acc[3][1] += a.w*b.y; acc[3][2] += a.w*b.z; acc[3][3] += a.w*b.w;
        }
        __syncthreads();
    }

#pragma unroll
    for (int ii = 0; ii < 4; ii++) {
        int m = m0 + ty*4 + ii;
#pragma unroll
        for (int jj = 0; jj < 4; jj++) {
            int n = n0 + tx*4 + jj;
            out[m*N + n] = acc[ii][jj] + bias[n];
        }
    }
}

extern "C" void kernel_launch(void* const* d_in, const int* in_sizes, int n_in,
                              void* d_out, int out_size)
{
    const float* x      = (const float*)d_in[0];
    const float* w_qkv  = (const float*)d_in[1];
    const float* b_qkv  = (const float*)d_in[2];
    const float* w_proj = (const float*)d_in[3];
    const float* b_proj = (const float*)d_in[4];
    float* out = (float*)d_out;

    dim3 g1(3072/64, (BB*SS)/64);   // 48 x 128
    qkv_gemm_kernel<<<g1, 256>>>(x, w_qkv, b_qkv);

    dim3 g2(SS/64, BB*HH);          // 32 x 64
    attn_kernel<<<g2, 256>>>();

    dim3 g3(1024/64, (BB*SS)/64);   // 16 x 128
    proj_gemm_kernel<<<g3, 256>>>(w_proj, b_proj, out);
}

// round 5
// speedup vs baseline: 2.2013x; 2.2013x over previous
#include <cuda_runtime.h>
#include <cuda_bf16.h>
#include <cstdint>

#define BB 4
#define SS 2048
#define DD 1024
#define HH 16
#define HD 64
#define SCALE 0.125f

// ---------------- scratch (__device__ globals; no allocs allowed) ----------
__device__ float g_q[BB*HH*SS*HD];
__device__ float g_k[BB*HH*SS*HD];
__device__ float g_v[BB*HH*SS*HD];
__device__ __nv_bfloat16 g_xh[BB*SS*DD];
__device__ __nv_bfloat16 g_xl[BB*SS*DD];
__device__ __nv_bfloat16 g_wqh[3*DD*DD];   // [N=3072, K=1024]  (W^T, K-major)
__device__ __nv_bfloat16 g_wql[3*DD*DD];
__device__ __nv_bfloat16 g_wph[DD*DD];     // [N=1024, K=1024]
__device__ __nv_bfloat16 g_wpl[DD*DD];
__device__ __nv_bfloat16 g_ch[BB*SS*DD];   // ctx hi
__device__ __nv_bfloat16 g_cl[BB*SS*DD];   // ctx lo

// ---------------- PTX helpers (sm_80-portable only) ------------------------
__device__ __forceinline__ uint32_t smem_u32(const void* p) {
    uint32_t a;
    asm("{ .reg .u64 t; cvta.to.shared.u64 t, %1; cvt.u32.u64 %0, t; }" : "=r"(a) : "l"(p));
    return a;
}
__device__ __forceinline__ void cp16(uint32_t s, const void* g) {
    asm volatile("cp.async.cg.shared.global [%0], [%1], 16;" :: "r"(s), "l"(g));
}
__device__ __forceinline__ void cp_commit() { asm volatile("cp.async.commit_group;"); }
template<int N> __device__ __forceinline__ void cp_wait() {
    asm volatile("cp.async.wait_group %0;" :: "n"(N));
}
__device__ __forceinline__ void ldsm4(uint32_t* r, uint32_t addr) {
    asm volatile("ldmatrix.sync.aligned.m8n8.x4.shared.b16 {%0,%1,%2,%3}, [%4];"
        : "=r"(r[0]), "=r"(r[1]), "=r"(r[2]), "=r"(r[3]) : "r"(addr));
}
__device__ __forceinline__ void mma16816(float* d, const uint32_t* a, const uint32_t* b) {
    asm volatile(
        "mma.sync.aligned.m16n8k16.row.col.f32.bf16.bf16.f32 "
        "{%0,%1,%2,%3}, {%4,%5,%6,%7}, {%8,%9}, {%0,%1,%2,%3};"
        : "+f"(d[0]), "+f"(d[1]), "+f"(d[2]), "+f"(d[3])
        : "r"(a[0]), "r"(a[1]), "r"(a[2]), "r"(a[3]), "r"(b[0]), "r"(b[1]));
}

// ---------------- convert kernels ------------------------------------------
__global__ __launch_bounds__(256) void convert_split4(const float4* __restrict__ in, int n4)
{
    int i = blockIdx.x * 256 + threadIdx.x;
    if (i >= n4) return;
    float4 v = in[i];
    union { __nv_bfloat16 b[4]; uint2 u; } H, L;
    H.b[0] = __float2bfloat16(v.x); L.b[0] = __float2bfloat16(v.x - __bfloat162float(H.b[0]));
    H.b[1] = __float2bfloat16(v.y); L.b[1] = __float2bfloat16(v.y - __bfloat162float(H.b[1]));
    H.b[2] = __float2bfloat16(v.z); L.b[2] = __float2bfloat16(v.z - __bfloat162float(H.b[2]));
    H.b[3] = __float2bfloat16(v.w); L.b[3] = __float2bfloat16(v.w - __bfloat162float(H.b[3]));
    ((uint2*)g_xh)[i] = H.u;
    ((uint2*)g_xl)[i] = L.u;
}

// W[K,N] row-major -> T[N,K] hi/lo bf16.  which: 0 = qkv, 1 = proj
__global__ __launch_bounds__(256) void convert_transpose(
    const float* __restrict__ W, int K, int N, int which)
{
    __shared__ float t[32][33];
    __nv_bfloat16* Th = which ? g_wph : g_wqh;
    __nv_bfloat16* Tl = which ? g_wpl : g_wql;
    int n0 = blockIdx.x * 32, k0 = blockIdx.y * 32;
    int tx = threadIdx.x, ty = threadIdx.y;   // 32 x 8
#pragma unroll
    for (int j = 0; j < 4; j++)
        t[ty + j*8][tx] = W[(size_t)(k0 + ty + j*8) * N + n0 + tx];
    __syncthreads();
#pragma unroll
    for (int j = 0; j < 4; j++) {
        float v = t[tx][ty + j*8];
        __nv_bfloat16 h = __float2bfloat16(v);
        __nv_bfloat16 l = __float2bfloat16(v - __bfloat162float(h));
        size_t o = (size_t)(n0 + ty + j*8) * K + k0 + tx;
        Th[o] = h; Tl[o] = l;
    }
}

// ---------------- bf16x3 GEMM via mma.sync (HMMA) ---------------------------
// C[8192, N] = A[8192,1024] @ B[N,1024]^T + bias
// mode 0: A = x hi/lo, B = w_qkv^T, scatter into g_q/g_k/g_v
// mode 1: A = ctx hi/lo, B = w_proj^T, out[m*1024+n]
//
// smem per stage: 4 parts (Ah,Al,Bh,Bl), each 128 rows x 32 bf16, row pitch
// 80B (16B-aligned; 80 mod 128 distinct over 8 rows -> ldmatrix conflict-free)
#define PART_BYTES  (128 * 80)          // 10240
#define STAGE_BYTES (4 * PART_BYTES)    // 40960
#define GSMEM_TOTAL (2 * STAGE_BYTES)   // 81920

__global__ __launch_bounds__(256, 1) void gemm_mma_bf16x3(
    const float* __restrict__ bias, int mode, float* __restrict__ out, int Ntot)
{
    extern __shared__ char smem[];
    const uint32_t sb = smem_u32(smem);
    const int tid  = threadIdx.x;
    const int lane = tid & 31, warp = tid >> 5;
    const int wm = warp >> 1, wn = warp & 1;       // 4 x 2 warp grid
    const int m0 = blockIdx.y * 128, n0 = blockIdx.x * 128;

    const __nv_bfloat16* Ah = mode ? g_ch : g_xh;
    const __nv_bfloat16* Al = mode ? g_cl : g_xl;
    const __nv_bfloat16* Bh = mode ? g_wph : g_wqh;
    const __nv_bfloat16* Bl = mode ? g_wpl : g_wql;

    float d[64];
#pragma unroll
    for (int i = 0; i < 64; i++) d[i] = 0.f;

    // ---- loader: chunk c (k0 = c*32) -> stage c&1 ------------------------
    auto load_chunk = [&](int c) {
        uint32_t st = sb + (uint32_t)(c & 1) * STAGE_BYTES;
        int k0 = c * 32;
#pragma unroll
        for (int i = 0; i < 8; i++) {
            int part  = i >> 1;                       // 0:Ah 1:Al 2:Bh 3:Bl
            int local = ((i & 1) << 8) + tid;         // 0..511
            int row   = local >> 2;
            int quad  = local & 3;
            uint32_t dst = st + (uint32_t)part * PART_BYTES + (uint32_t)row * 80 + (uint32_t)quad * 16;
            size_t go = (size_t)((part < 2 ? m0 : n0) + row) * 1024 + k0 + quad * 8;
            const __nv_bfloat16* src =
                (part == 0) ? Ah : (part == 1) ? Al : (part == 2) ? Bh : Bl;
            cp16(dst, src + go);
        }
        cp_commit();
    };

    // fragment address components
    const uint32_t a_row = (uint32_t)(wm * 32 + (lane & 15));
    const uint32_t a_kb  = (uint32_t)((lane >> 4) * 16);
    const uint32_t b_row = (uint32_t)(wn * 64 + (lane & 7) + ((lane & 16) ? 8 : 0));
    const uint32_t b_kb  = (uint32_t)((lane & 8) ? 16 : 0);

    const int NCHUNK = 32;   // K=1024 / 32
    load_chunk(0);
    for (int c = 0; c < NCHUNK; c++) {
        if (c + 1 < NCHUNK) { load_chunk(c + 1); cp_wait<1>(); }
        else                { cp_wait<0>(); }
        __syncthreads();

        uint32_t st = sb + (uint32_t)(c & 1) * STAGE_BYTES;
#pragma unroll
        for (int ks = 0; ks < 2; ks++) {
            uint32_t kb = (uint32_t)ks * 32;
            uint32_t ah[2][4], al[2][4], bh[4][4], bl[4][4];
#pragma unroll
            for (int mi = 0; mi < 2; mi++) {
                uint32_t ro = (a_row + mi * 16) * 80 + kb + a_kb;
                ldsm4(ah[mi], st + ro);
                ldsm4(al[mi], st + PART_BYTES + ro);
            }
#pragma unroll
            for (int ni = 0; ni < 4; ni++) {
                uint32_t ro = (b_row + ni * 16) * 80 + kb + b_kb;
                ldsm4(bh[ni], st + 2 * PART_BYTES + ro);
                ldsm4(bl[ni], st + 3 * PART_BYTES + ro);
            }
#pragma unroll
            for (int mi = 0; mi < 2; mi++)
#pragma unroll
                for (int nb = 0; nb < 8; nb++) {
                    float* dp = d + (mi * 8 + nb) * 4;
                    const uint32_t* bph = &bh[nb >> 1][(nb & 1) * 2];
                    const uint32_t* bpl = &bl[nb >> 1][(nb & 1) * 2];
                    mma16816(dp, ah[mi], bph);
                    mma16816(dp, al[mi], bph);
                    mma16816(dp, ah[mi], bpl);
                }
        }
        __syncthreads();
    }

    // ---- epilogue --------------------------------------------------------
    const int r = lane >> 2, cpair = (lane & 3) * 2;
    const int three = n0 >> 10, rem0 = n0 & 1023;
    float* qkv_dst = (three == 0) ? g_q : (three == 1) ? g_k : g_v;

#pragma unroll
    for (int mi = 0; mi < 2; mi++)
#pragma unroll
        for (int nb = 0; nb < 8; nb++) {
            float* dp = d + (mi * 8 + nb) * 4;
            int m_top = m0 + wm * 32 + mi * 16 + r;
            int n = n0 + wn * 64 + nb * 8 + cpair;
            float bx = __ldg(bias + n), by = __ldg(bias + n + 1);
            float2 v0 = make_float2(dp[0] + bx, dp[1] + by);
            float2 v1 = make_float2(dp[2] + bx, dp[3] + by);
            if (mode == 0) {
                int nrem = (rem0 + (n - n0));
                int h = nrem >> 6, dd2 = nrem & 63;
                int b0i = m_top >> 11, s0i = m_top & 2047;
                int b1i = (m_top + 8) >> 11, s1i = (m_top + 8) & 2047;
                *(float2*)(qkv_dst + ((size_t)(b0i*HH + h)*SS + s0i)*HD + dd2) = v0;
                *(float2*)(qkv_dst + ((size_t)(b1i*HH + h)*SS + s1i)*HD + dd2) = v1;
            } else {
                *(float2*)(out + (size_t)m_top * 1024 + n) = v0;
                *(float2*)(out + (size_t)(m_top + 8) * 1024 + n) = v1;
            }
        }
}

// ---------------- flash attention (fp32 SIMT) ------------------------------
__global__ __launch_bounds__(256) void attn_kernel()
{
    __shared__ float Qt[64][68];
    __shared__ float Kt[64][36];
    __shared__ float Vs[32][64];
    __shared__ float St[32][68];
    __shared__ float m_s[64], l_s[64], alpha_s[64];
    __shared__ float pmax[4][64], psum[4][64];

    int tid = threadIdx.x;
    int bh  = blockIdx.y;
    int q0  = blockIdx.x * 64;

    const float* Qg = g_q + (size_t)(bh*SS + q0)*HD;
    const float* Kg = g_k + (size_t)bh*SS*HD;
    const float* Vg = g_v + (size_t)bh*SS*HD;

    {
        int r = tid >> 2;
#pragma unroll
        for (int q = 0; q < 4; q++) {
            int c = ((tid & 3) * 4 + q) * 4;
            float4 v = *(const float4*)(Qg + r*HD + c);
            Qt[c+0][r] = v.x*SCALE; Qt[c+1][r] = v.y*SCALE;
            Qt[c+2][r] = v.z*SCALE; Qt[c+3][r] = v.w*SCALE;
        }
    }
    if (tid < 64) { m_s[tid] = -1e30f; l_s[tid] = 0.f; }

    int ty = tid >> 4, tx = tid & 15;
    int si = tid & 63, wj = tid >> 6;

    float oacc[4][4];
#pragma unroll
    for (int i = 0; i < 4; i++)
#pragma unroll
        for (int j = 0; j < 4; j++) oacc[i][j] = 0.f;

    for (int kv0 = 0; kv0 < SS; kv0 += 32) {
        {
            int r = tid >> 3;
#pragma unroll
            for (int q = 0; q < 2; q++) {
                int c = (tid & 7) * 8 + q * 4;
                float4 kv = *(const float4*)(Kg + (size_t)(kv0 + r)*HD + c);
                Kt[c+0][r] = kv.x; Kt[c+1][r] = kv.y;
                Kt[c+2][r] = kv.z; Kt[c+3][r] = kv.w;
                float4 vv = *(const float4*)(Vg + (size_t)(kv0 + r)*HD + c);
                *(float4*)&Vs[r][c] = vv;
            }
        }
        __syncthreads();

        {
            float sacc[4][2];
#pragma unroll
            for (int i = 0; i < 4; i++) { sacc[i][0] = 0.f; sacc[i][1] = 0.f; }
#pragma unroll 8
            for (int dix = 0; dix < 64; dix++) {
                float4 a = *(const float4*)&Qt[dix][ty*4];
                float2 bq = *(const float2*)&Kt[dix][tx*2];
                sacc[0][0] += a.x*bq.x; sacc[0][1] += a.x*bq.y;
                sacc[1][0] += a.y*bq.x; sacc[1][1] += a.y*bq.y;
                sacc[2][0] += a.z*bq.x; sacc[2][1] += a.z*bq.y;
                sacc[3][0] += a.w*bq.x; sacc[3][1] += a.w*bq.y;
            }
#pragma unroll
            for (int ii = 0; ii < 4; ii++) {
                St[tx*2+0][ty*4+ii] = sacc[ii][0];
                St[tx*2+1][ty*4+ii] = sacc[ii][1];
            }
        }
        __syncthreads();

        float mold = m_s[si];
        float lmax = -1e30f;
#pragma unroll
        for (int j = wj*8; j < wj*8 + 8; j++) lmax = fmaxf(lmax, St[j][si]);
        pmax[wj][si] = lmax;
        __syncthreads();

        float mnew = fmaxf(mold,
                     fmaxf(fmaxf(pmax[0][si], pmax[1][si]),
                           fmaxf(pmax[2][si], pmax[3][si])));
        float lsum = 0.f;
#pragma unroll
        for (int j = wj*8; j < wj*8 + 8; j++) {
            float p = __expf(St[j][si] - mnew);
            St[j][si] = p;
            lsum += p;
        }
        psum[wj][si] = lsum;
        __syncthreads();

        if (wj == 0) {
            float rs = psum[0][si] + psum[1][si] + psum[2][si] + psum[3][si];
            float alpha = __expf(mold - mnew);
            alpha_s[si] = alpha;
            l_s[si] = l_s[si] * alpha + rs;
            m_s[si] = mnew;
        }
        __syncthreads();

        {
            float a0 = alpha_s[ty*4+0], a1 = alpha_s[ty*4+1];
            float a2 = alpha_s[ty*4+2], a3 = alpha_s[ty*4+3];
#pragma unroll
            for (int j = 0; j < 4; j++) {
                oacc[0][j] *= a0; oacc[1][j] *= a1;
                oacc[2][j] *= a2; oacc[3][j] *= a3;
            }
#pragma unroll 8
            for (int k = 0; k < 32; k++) {
                float4 a = *(const float4*)&St[k][ty*4];
                float4 bq = *(const float4*)&Vs[k][tx*4];
                oacc[0][0] += a.x*bq.x; oacc[0][1] += a.x*bq.y; oacc[0][2] += a.x*bq.z; oacc[0][3] += a.x*bq.w;
                oacc[1][0] += a.y*bq.x; oacc[1][1] += a.y*bq.y; oacc[1][2] += a.y*bq.z; oacc[1][3] += a.y*bq.w;
                oacc[2][0] += a.z*bq.x; oacc[2][1] += a.z*bq.y; oacc[2][2] += a.z*bq.z; oacc[2][3] += a.z*bq.w;
                oacc[3][0] += a.w*bq.x; oacc[3][1] += a.w*bq.y; oacc[3][2] += a.w*bq.z; oacc[3][3] += a.w*bq.w;
            }
        }
        __syncthreads();
    }

    // epilogue: ctx -> bf16 hi/lo split for proj GEMM
    int b = bh >> 4, h = bh & 15;
#pragma unroll
    for (int ii = 0; ii < 4; ii++) {
        int srow = q0 + ty*4 + ii;
        float inv = 1.0f / l_s[ty*4+ii];
        float o0 = oacc[ii][0]*inv, o1 = oacc[ii][1]*inv;
        float o2 = oacc[ii][2]*inv, o3 = oacc[ii][3]*inv;
        union { __nv_bfloat16 bb[4]; uint2 u; } H, L;
        H.bb[0] = __float2bfloat16(o0); L.bb[0] = __float2bfloat16(o0 - __bfloat162float(H.bb[0]));
        H.bb[1] = __float2bfloat16(o1); L.bb[1] = __float2bfloat16(o1 - __bfloat162float(H.bb[1]));
        H.bb[2] = __float2bfloat16(o2); L.bb[2] = __float2bfloat16(o2 - __bfloat162float(H.bb[2]));
        H.bb[3] = __float2bfloat16(o3); L.bb[3] = __float2bfloat16(o3 - __bfloat162float(H.bb[3]));
        size_t base = ((size_t)(b*SS + srow))*DD + h*HD + tx*4;
        *(uint2*)(g_ch + base) = H.u;
        *(uint2*)(g_cl + base) = L.u;
    }
}

// ---------------------------------------------------------------------------
extern "C" void kernel_launch(void* const* d_in, const int* in_sizes, int n_in,
                              void* d_out, int out_size)
{
    const float* x      = (const float*)d_in[0];
    const float* w_qkv  = (const float*)d_in[1];
    const float* b_qkv  = (const float*)d_in[2];
    const float* w_proj = (const float*)d_in[3];
    const float* b_proj = (const float*)d_in[4];
    float* out = (float*)d_out;

    cudaFuncSetAttribute(gemm_mma_bf16x3,
                         cudaFuncAttributeMaxDynamicSharedMemorySize, GSMEM_TOTAL);

    int nx4 = BB*SS*DD/4;
    convert_split4<<<(nx4 + 255)/256, 256>>>((const float4*)x, nx4);
    convert_transpose<<<dim3(3*DD/32, DD/32), dim3(32, 8)>>>(w_qkv, DD, 3*DD, 0);
    convert_transpose<<<dim3(DD/32, DD/32), dim3(32, 8)>>>(w_proj, DD, DD, 1);

    gemm_mma_bf16x3<<<dim3(3*DD/128, BB*SS/128), 256, GSMEM_TOTAL>>>(b_qkv, 0, nullptr, 3*DD);

    attn_kernel<<<dim3(SS/64, BB*HH), 256>>>();

    gemm_mma_bf16x3<<<dim3(DD/128, BB*SS/128), 256, GSMEM_TOTAL>>>(b_proj, 1, out, DD);
}

// round 6
// speedup vs baseline: 5.5398x; 2.5166x over previous
#include <cuda_runtime.h>
#include <cuda_bf16.h>
#include <cstdint>

#define BB 4
#define SS 2048
#define DD 1024
#define HH 16
#define HD 64
#define SCALE 0.125f

// ---------------- scratch (__device__ globals; no allocs allowed) ----------
__device__ __nv_bfloat16 g_xh[BB*SS*DD];
__device__ __nv_bfloat16 g_xl[BB*SS*DD];
__device__ __nv_bfloat16 g_wqh[3*DD*DD];   // [N=3072, K=1024]  (W^T, K-major)
__device__ __nv_bfloat16 g_wql[3*DD*DD];
__device__ __nv_bfloat16 g_wph[DD*DD];     // [N=1024, K=1024]
__device__ __nv_bfloat16 g_wpl[DD*DD];
__device__ __nv_bfloat16 g_qh[BB*HH*SS*HD];   // Q (pre-scaled) [B,H,S,64]
__device__ __nv_bfloat16 g_ql[BB*HH*SS*HD];
__device__ __nv_bfloat16 g_kh[BB*HH*SS*HD];   // K [B,H,S,64]
__device__ __nv_bfloat16 g_kl[BB*HH*SS*HD];
__device__ __nv_bfloat16 g_vth[BB*HH*HD*SS];  // V^T [B,H,64,S]
__device__ __nv_bfloat16 g_vtl[BB*HH*HD*SS];
__device__ __nv_bfloat16 g_ch[BB*SS*DD];      // ctx hi
__device__ __nv_bfloat16 g_cl[BB*SS*DD];      // ctx lo

// ---------------- PTX helpers (sm_80-portable only) ------------------------
__device__ __forceinline__ uint32_t smem_u32(const void* p) {
    uint32_t a;
    asm("{ .reg .u64 t; cvta.to.shared.u64 t, %1; cvt.u32.u64 %0, t; }" : "=r"(a) : "l"(p));
    return a;
}
__device__ __forceinline__ void cp16(uint32_t s, const void* g) {
    asm volatile("cp.async.cg.shared.global [%0], [%1], 16;" :: "r"(s), "l"(g));
}
__device__ __forceinline__ void cp_commit() { asm volatile("cp.async.commit_group;"); }
template<int N> __device__ __forceinline__ void cp_wait() {
    asm volatile("cp.async.wait_group %0;" :: "n"(N));
}
__device__ __forceinline__ void ldsm4(uint32_t* r, uint32_t addr) {
    asm volatile("ldmatrix.sync.aligned.m8n8.x4.shared.b16 {%0,%1,%2,%3}, [%4];"
        : "=r"(r[0]), "=r"(r[1]), "=r"(r[2]), "=r"(r[3]) : "r"(addr));
}
__device__ __forceinline__ void mma16816(float* d, const uint32_t* a, const uint32_t* b) {
    asm volatile(
        "mma.sync.aligned.m16n8k16.row.col.f32.bf16.bf16.f32 "
        "{%0,%1,%2,%3}, {%4,%5,%6,%7}, {%8,%9}, {%0,%1,%2,%3};"
        : "+f"(d[0]), "+f"(d[1]), "+f"(d[2]), "+f"(d[3])
        : "r"(a[0]), "r"(a[1]), "r"(a[2]), "r"(a[3]), "r"(b[0]), "r"(b[1]));
}
// pack two f32 -> bf16x2 (lo in low half)
__device__ __forceinline__ uint32_t packbf(float lo, float hi) {
    uint32_t r;
    asm("cvt.rn.bf16x2.f32 %0, %1, %2;" : "=r"(r) : "f"(hi), "f"(lo));
    return r;
}
__device__ __forceinline__ float bflo(uint32_t p) { return __uint_as_float(p << 16); }
__device__ __forceinline__ float bfhi(uint32_t p) { return __uint_as_float(p & 0xffff0000u); }

// ---------------- convert kernels ------------------------------------------
__global__ __launch_bounds__(256) void convert_split4(const float4* __restrict__ in, int n4)
{
    int i = blockIdx.x * 256 + threadIdx.x;
    if (i >= n4) return;
    float4 v = in[i];
    uint32_t h0 = packbf(v.x, v.y);
    uint32_t l0 = packbf(v.x - bflo(h0), v.y - bfhi(h0));
    uint32_t h1 = packbf(v.z, v.w);
    uint32_t l1 = packbf(v.z - bflo(h1), v.w - bfhi(h1));
    ((uint2*)g_xh)[i] = make_uint2(h0, h1);
    ((uint2*)g_xl)[i] = make_uint2(l0, l1);
}

// W[K,N] row-major -> T[N,K] hi/lo bf16.  which: 0 = qkv, 1 = proj
__global__ __launch_bounds__(256) void convert_transpose(
    const float* __restrict__ W, int K, int N, int which)
{
    __shared__ float t[32][33];
    __nv_bfloat16* Th = which ? g_wph : g_wqh;
    __nv_bfloat16* Tl = which ? g_wpl : g_wql;
    int n0 = blockIdx.x * 32, k0 = blockIdx.y * 32;
    int tx = threadIdx.x, ty = threadIdx.y;   // 32 x 8
#pragma unroll
    for (int j = 0; j < 4; j++)
        t[ty + j*8][tx] = W[(size_t)(k0 + ty + j*8) * N + n0 + tx];
    __syncthreads();
#pragma unroll
    for (int j = 0; j < 4; j++) {
        float v = t[tx][ty + j*8];
        __nv_bfloat16 h = __float2bfloat16(v);
        __nv_bfloat16 l = __float2bfloat16(v - __bfloat162float(h));
        size_t o = (size_t)(n0 + ty + j*8) * K + k0 + tx;
        Th[o] = h; Tl[o] = l;
    }
}

// ---------------- bf16x3 GEMM via mma.sync (HMMA) ---------------------------
#define PART_BYTES  (128 * 80)
#define STAGE_BYTES (4 * PART_BYTES)
#define GSMEM_TOTAL (2 * STAGE_BYTES)   // 81920

__global__ __launch_bounds__(256, 2) void gemm_mma_bf16x3(
    const float* __restrict__ bias, int mode, float* __restrict__ out)
{
    extern __shared__ char smem[];
    const uint32_t sb = smem_u32(smem);
    const int tid  = threadIdx.x;
    const int lane = tid & 31, warp = tid >> 5;
    const int wm = warp >> 1, wn = warp & 1;       // 4 x 2 warp grid
    const int m0 = blockIdx.y * 128, n0 = blockIdx.x * 128;

    const __nv_bfloat16* Ah = mode ? g_ch : g_xh;
    const __nv_bfloat16* Al = mode ? g_cl : g_xl;
    const __nv_bfloat16* Bh = mode ? g_wph : g_wqh;
    const __nv_bfloat16* Bl = mode ? g_wpl : g_wql;

    float d[64];
#pragma unroll
    for (int i = 0; i < 64; i++) d[i] = 0.f;

    auto load_chunk = [&](int c) {
        uint32_t st = sb + (uint32_t)(c & 1) * STAGE_BYTES;
        int k0 = c * 32;
#pragma unroll
        for (int i = 0; i < 8; i++) {
            int part  = i >> 1;
            int local = ((i & 1) << 8) + tid;
            int row   = local >> 2;
            int quad  = local & 3;
            uint32_t dst = st + (uint32_t)part * PART_BYTES + (uint32_t)row * 80 + (uint32_t)quad * 16;
            size_t go = (size_t)((part < 2 ? m0 : n0) + row) * 1024 + k0 + quad * 8;
            const __nv_bfloat16* src =
                (part == 0) ? Ah : (part == 1) ? Al : (part == 2) ? Bh : Bl;
            cp16(dst, src + go);
        }
        cp_commit();
    };

    const uint32_t a_row = (uint32_t)(wm * 32 + (lane & 15));
    const uint32_t a_kb  = (uint32_t)((lane >> 4) * 16);
    const uint32_t b_row = (uint32_t)(wn * 64 + (lane & 7) + ((lane & 16) ? 8 : 0));
    const uint32_t b_kb  = (uint32_t)((lane & 8) ? 16 : 0);

    const int NCHUNK = 32;
    load_chunk(0);
    for (int c = 0; c < NCHUNK; c++) {
        if (c + 1 < NCHUNK) { load_chunk(c + 1); cp_wait<1>(); }
        else                { cp_wait<0>(); }
        __syncthreads();

        uint32_t st = sb + (uint32_t)(c & 1) * STAGE_BYTES;
#pragma unroll
        for (int ks = 0; ks < 2; ks++) {
            uint32_t kb = (uint32_t)ks * 32;
            uint32_t ah[2][4], al[2][4], bh[4][4], bl[4][4];
#pragma unroll
            for (int mi = 0; mi < 2; mi++) {
                uint32_t ro = (a_row + mi * 16) * 80 + kb + a_kb;
                ldsm4(ah[mi], st + ro);
                ldsm4(al[mi], st + PART_BYTES + ro);
            }
#pragma unroll
            for (int ni = 0; ni < 4; ni++) {
                uint32_t ro = (b_row + ni * 16) * 80 + kb + b_kb;
                ldsm4(bh[ni], st + 2 * PART_BYTES + ro);
                ldsm4(bl[ni], st + 3 * PART_BYTES + ro);
            }
#pragma unroll
            for (int mi = 0; mi < 2; mi++)
#pragma unroll
                for (int nb = 0; nb < 8; nb++) {
                    float* dp = d + (mi * 8 + nb) * 4;
                    const uint32_t* bph = &bh[nb >> 1][(nb & 1) * 2];
                    const uint32_t* bpl = &bl[nb >> 1][(nb & 1) * 2];
                    mma16816(dp, ah[mi], bph);
                    mma16816(dp, al[mi], bph);
                    mma16816(dp, ah[mi], bpl);
                }
        }
        __syncthreads();
    }

    // ---- epilogue --------------------------------------------------------
    const int r = lane >> 2, cpair = (lane & 3) * 2;
    const int three = n0 >> 10, rem0 = n0 & 1023;

#pragma unroll
    for (int mi = 0; mi < 2; mi++)
#pragma unroll
        for (int nb = 0; nb < 8; nb++) {
            float* dp = d + (mi * 8 + nb) * 4;
            int m_top = m0 + wm * 32 + mi * 16 + r;
            int nofs = wn * 64 + nb * 8 + cpair;
            int n = n0 + nofs;
            float bx = __ldg(bias + n), by = __ldg(bias + n + 1);
            float v00 = dp[0] + bx, v01 = dp[1] + by;   // row m_top
            float v10 = dp[2] + bx, v11 = dp[3] + by;   // row m_top+8
            if (mode == 1) {
                *(float2*)(out + (size_t)m_top * 1024 + n) = make_float2(v00, v01);
                *(float2*)(out + (size_t)(m_top + 8) * 1024 + n) = make_float2(v10, v11);
                continue;
            }
            int nrem = rem0 + nofs;
            int h = nrem >> 6, dd2 = nrem & 63;
            int bh0 = (m_top >> 11) * HH + h;           int s0 = m_top & 2047;
            int bh1 = ((m_top + 8) >> 11) * HH + h;     int s1 = (m_top + 8) & 2047;
            if (three == 2) {
                // V: transposed store [B,H,64,S]
                uint32_t H0 = packbf(v00, v01), L0 = packbf(v00 - bflo(H0), v01 - bfhi(H0));
                uint32_t H1 = packbf(v10, v11), L1 = packbf(v10 - bflo(H1), v11 - bfhi(H1));
                size_t r0 = ((size_t)bh0 * HD + dd2) * SS;
                size_t r1 = ((size_t)bh1 * HD + dd2) * SS;
                g_vth[r0 + s0]      = __ushort_as_bfloat16((unsigned short)(H0 & 0xffff));
                g_vth[r0 + SS + s0] = __ushort_as_bfloat16((unsigned short)(H0 >> 16));
                g_vtl[r0 + s0]      = __ushort_as_bfloat16((unsigned short)(L0 & 0xffff));
                g_vtl[r0 + SS + s0] = __ushort_as_bfloat16((unsigned short)(L0 >> 16));
                g_vth[r1 + s1]      = __ushort_as_bfloat16((unsigned short)(H1 & 0xffff));
                g_vth[r1 + SS + s1] = __ushort_as_bfloat16((unsigned short)(H1 >> 16));
                g_vtl[r1 + s1]      = __ushort_as_bfloat16((unsigned short)(L1 & 0xffff));
                g_vtl[r1 + SS + s1] = __ushort_as_bfloat16((unsigned short)(L1 >> 16));
            } else {
                __nv_bfloat16 *Hdst, *Ldst;
                if (three == 0) { v00 *= SCALE; v01 *= SCALE; v10 *= SCALE; v11 *= SCALE;
                                  Hdst = g_qh; Ldst = g_ql; }
                else            { Hdst = g_kh; Ldst = g_kl; }
                uint32_t H0 = packbf(v00, v01), L0 = packbf(v00 - bflo(H0), v01 - bfhi(H0));
                uint32_t H1 = packbf(v10, v11), L1 = packbf(v10 - bflo(H1), v11 - bfhi(H1));
                size_t i0 = ((size_t)bh0 * SS + s0) * HD + dd2;
                size_t i1 = ((size_t)bh1 * SS + s1) * HD + dd2;
                *(uint32_t*)(Hdst + i0) = H0;  *(uint32_t*)(Ldst + i0) = L0;
                *(uint32_t*)(Hdst + i1) = H1;  *(uint32_t*)(Ldst + i1) = L1;
            }
        }
}

// ---------------- flash attention via mma.sync ------------------------------
// grid (S/128, B*H), 256 threads (8 warps), each warp owns 16 query rows.
// smem: 4 buffers (Kh,Kl,Vth,Vtl) x 2 stages x (64 rows x 144B) = 73728B
#define AT_ROWB   144
#define AT_STAGE  9216          // 64 * 144
#define AT_BUF    (2 * AT_STAGE)
#define AT_SMEM   (4 * AT_BUF)  // 73728

__global__ __launch_bounds__(256) void attn_mma()
{
    extern __shared__ char smem[];
    const uint32_t sb = smem_u32(smem);
    const int tid = threadIdx.x;
    const int lane = tid & 31, w = tid >> 5;
    const int bh = blockIdx.y;
    const int q0 = blockIdx.x * 128;

    const __nv_bfloat16* Kh = g_kh + (size_t)bh * SS * HD;
    const __nv_bfloat16* Kl = g_kl + (size_t)bh * SS * HD;
    const __nv_bfloat16* Vth = g_vth + (size_t)bh * HD * SS;
    const __nv_bfloat16* Vtl = g_vtl + (size_t)bh * HD * SS;

    // ---- preload Q fragments (scaled hi/lo) via K buffers ----------------
    {
        const __nv_bfloat16* Qh = g_qh + ((size_t)bh * SS + q0) * HD;
        const __nv_bfloat16* Ql = g_ql + ((size_t)bh * SS + q0) * HD;
#pragma unroll
        for (int i = 0; i < 8; i++) {
            int unit = i * 256 + tid;           // 0..2047
            int buf = unit >> 10;               // 0=hi 1=lo
            int rem = unit & 1023;
            int row = rem >> 3, ch = rem & 7;
            uint32_t dst = sb + (uint32_t)buf * AT_BUF + (uint32_t)row * AT_ROWB + (uint32_t)ch * 16;
            const __nv_bfloat16* src = buf ? Ql : Qh;
            cp16(dst, src + (size_t)row * HD + ch * 8);
        }
        cp_commit();
    }
    cp_wait<0>();
    __syncthreads();

    uint32_t qh[4][4], ql[4][4];
    {
        uint32_t a_row = (uint32_t)(w * 16 + (lane & 15));
        uint32_t a_kb  = (uint32_t)((lane >> 4) * 16);
#pragma unroll
        for (int kc = 0; kc < 4; kc++) {
            uint32_t ro = a_row * AT_ROWB + (uint32_t)kc * 32 + a_kb;
            ldsm4(qh[kc], sb + ro);
            ldsm4(ql[kc], sb + AT_BUF + ro);
        }
    }
    __syncthreads();

    // ---- kv tile loader ---------------------------------------------------
    auto load_tile = [&](int t) {
        int kv0 = t * 64;
        uint32_t st = sb + (uint32_t)(t & 1) * AT_STAGE;
#pragma unroll
        for (int i = 0; i < 8; i++) {
            int unit = i * 256 + tid;           // 0..2047
            int buf = unit >> 9;                // 0:Kh 1:Kl 2:Vth 3:Vtl
            int rem = unit & 511;
            int row = rem >> 3, ch = rem & 7;
            uint32_t dst = st + (uint32_t)buf * AT_BUF + (uint32_t)row * AT_ROWB + (uint32_t)ch * 16;
            const void* src;
            if (buf < 2) {
                const __nv_bfloat16* p = buf ? Kl : Kh;
                src = p + ((size_t)(kv0 + row)) * HD + ch * 8;
            } else {
                const __nv_bfloat16* p = (buf == 2) ? Vth : Vtl;
                src = p + (size_t)row * SS + kv0 + ch * 8;
            }
            cp16(dst, src);
        }
        cp_commit();
    };

    float o[8][4];
#pragma unroll
    for (int j = 0; j < 8; j++)
#pragma unroll
        for (int k = 0; k < 4; k++) o[j][k] = 0.f;
    float m0 = -1e30f, m1 = -1e30f, l0 = 0.f, l1 = 0.f;

    const uint32_t b_row_off = (uint32_t)((lane & 7) + ((lane & 16) ? 8 : 0));
    const uint32_t b_kb = (uint32_t)((lane & 8) ? 16 : 0);

    load_tile(0);
    for (int t = 0; t < SS / 64; t++) {
        if (t + 1 < SS / 64) { load_tile(t + 1); cp_wait<1>(); }
        else                 { cp_wait<0>(); }
        __syncthreads();

        uint32_t st = sb + (uint32_t)(t & 1) * AT_STAGE;

        // ---- S = Q K^T (bf16x3) -----------------------------------------
        float s[8][4];
#pragma unroll
        for (int j = 0; j < 8; j++)
#pragma unroll
            for (int k = 0; k < 4; k++) s[j][k] = 0.f;

#pragma unroll
        for (int kc = 0; kc < 4; kc++) {
#pragma unroll
            for (int ni = 0; ni < 4; ni++) {
                uint32_t ro = ((uint32_t)(ni * 16) + b_row_off) * AT_ROWB + (uint32_t)kc * 32 + b_kb;
                uint32_t bh4[4], bl4[4];
                ldsm4(bh4, st + ro);
                ldsm4(bl4, st + AT_BUF + ro);
#pragma unroll
                for (int hf = 0; hf < 2; hf++) {
                    float* sp = s[ni * 2 + hf];
                    mma16816(sp, qh[kc], &bh4[hf * 2]);
                    mma16816(sp, ql[kc], &bh4[hf * 2]);
                    mma16816(sp, qh[kc], &bl4[hf * 2]);
                }
            }
        }

        // ---- online softmax (rows owned by quad lanes) -------------------
        float mx0 = s[0][0], mx1 = s[0][2];
#pragma unroll
        for (int j = 0; j < 8; j++) {
            mx0 = fmaxf(mx0, fmaxf(s[j][0], s[j][1]));
            mx1 = fmaxf(mx1, fmaxf(s[j][2], s[j][3]));
        }
        mx0 = fmaxf(mx0, __shfl_xor_sync(0xffffffffu, mx0, 1));
        mx0 = fmaxf(mx0, __shfl_xor_sync(0xffffffffu, mx0, 2));
        mx1 = fmaxf(mx1, __shfl_xor_sync(0xffffffffu, mx1, 1));
        mx1 = fmaxf(mx1, __shfl_xor_sync(0xffffffffu, mx1, 2));
        float mn0 = fmaxf(m0, mx0), mn1 = fmaxf(m1, mx1);
        float al0 = __expf(m0 - mn0), al1 = __expf(m1 - mn1);
        float sum0 = 0.f, sum1 = 0.f;
#pragma unroll
        for (int j = 0; j < 8; j++) {
            s[j][0] = __expf(s[j][0] - mn0); sum0 += s[j][0];
            s[j][1] = __expf(s[j][1] - mn0); sum0 += s[j][1];
            s[j][2] = __expf(s[j][2] - mn1); sum1 += s[j][2];
            s[j][3] = __expf(s[j][3] - mn1); sum1 += s[j][3];
        }
        sum0 += __shfl_xor_sync(0xffffffffu, sum0, 1);
        sum0 += __shfl_xor_sync(0xffffffffu, sum0, 2);
        sum1 += __shfl_xor_sync(0xffffffffu, sum1, 1);
        sum1 += __shfl_xor_sync(0xffffffffu, sum1, 2);
        l0 = l0 * al0 + sum0; l1 = l1 * al1 + sum1;
        m0 = mn0; m1 = mn1;
#pragma unroll
        for (int j = 0; j < 8; j++) {
            o[j][0] *= al0; o[j][1] *= al0;
            o[j][2] *= al1; o[j][3] *= al1;
        }

        // ---- O += P V (bf16x3), A-frags repacked from S accum ------------
#pragma unroll
        for (int kvc = 0; kvc < 4; kvc++) {
            uint32_t ah4[4], al4[4];
            {
                float* p0 = s[kvc * 2];
                float* p1 = s[kvc * 2 + 1];
                ah4[0] = packbf(p0[0], p0[1]);
                al4[0] = packbf(p0[0] - bflo(ah4[0]), p0[1] - bfhi(ah4[0]));
                ah4[1] = packbf(p0[2], p0[3]);
                al4[1] = packbf(p0[2] - bflo(ah4[1]), p0[3] - bfhi(ah4[1]));
                ah4[2] = packbf(p1[0], p1[1]);
                al4[2] = packbf(p1[0] - bflo(ah4[2]), p1[1] - bfhi(ah4[2]));
                ah4[3] = packbf(p1[2], p1[3]);
                al4[3] = packbf(p1[2] - bflo(ah4[3]), p1[3] - bfhi(ah4[3]));
            }
#pragma unroll
            for (int ni = 0; ni < 4; ni++) {
                uint32_t ro = ((uint32_t)(ni * 16) + b_row_off) * AT_ROWB + (uint32_t)kvc * 32 + b_kb;
                uint32_t bh4[4], bl4[4];
                ldsm4(bh4, st + 2 * AT_BUF + ro);
                ldsm4(bl4, st + 3 * AT_BUF + ro);
#pragma unroll
                for (int hf = 0; hf < 2; hf++) {
                    float* op = o[ni * 2 + hf];
                    mma16816(op, ah4, &bh4[hf * 2]);
                    mma16816(op, al4, &bh4[hf * 2]);
                    mma16816(op, ah4, &bl4[hf * 2]);
                }
            }
        }
        __syncthreads();
    }

    // ---- write ctx hi/lo --------------------------------------------------
    const int r = lane >> 2, cpair = (lane & 3) * 2;
    const int b = bh >> 4, h = bh & 15;
    float inv0 = 1.f / l0, inv1 = 1.f / l1;
    int row0 = q0 + w * 16 + r, row1 = row0 + 8;
#pragma unroll
    for (int j = 0; j < 8; j++) {
        int col = h * HD + j * 8 + cpair;
        float v00 = o[j][0] * inv0, v01 = o[j][1] * inv0;
        float v10 = o[j][2] * inv1, v11 = o[j][3] * inv1;
        uint32_t H0 = packbf(v00, v01), L0 = packbf(v00 - bflo(H0), v01 - bfhi(H0));
        uint32_t H1 = packbf(v10, v11), L1 = packbf(v10 - bflo(H1), v11 - bfhi(H1));
        size_t i0 = ((size_t)b * SS + row0) * DD + col;
        size_t i1 = ((size_t)b * SS + row1) * DD + col;
        *(uint32_t*)(g_ch + i0) = H0;  *(uint32_t*)(g_cl + i0) = L0;
        *(uint32_t*)(g_ch + i1) = H1;  *(uint32_t*)(g_cl + i1) = L1;
    }
}

// ---------------------------------------------------------------------------
extern "C" void kernel_launch(void* const* d_in, const int* in_sizes, int n_in,
                              void* d_out, int out_size)
{
    const float* x      = (const float*)d_in[0];
    const float* w_qkv  = (const float*)d_in[1];
    const float* b_qkv  = (const float*)d_in[2];
    const float* w_proj = (const float*)d_in[3];
    const float* b_proj = (const float*)d_in[4];
    float* out = (float*)d_out;

    cudaFuncSetAttribute(gemm_mma_bf16x3,
                         cudaFuncAttributeMaxDynamicSharedMemorySize, GSMEM_TOTAL);
    cudaFuncSetAttribute(attn_mma,
                         cudaFuncAttributeMaxDynamicSharedMemorySize, AT_SMEM);

    int nx4 = BB*SS*DD/4;
    convert_split4<<<(nx4 + 255)/256, 256>>>((const float4*)x, nx4);
    convert_transpose<<<dim3(3*DD/32, DD/32), dim3(32, 8)>>>(w_qkv, DD, 3*DD, 0);
    convert_transpose<<<dim3(DD/32, DD/32), dim3(32, 8)>>>(w_proj, DD, DD, 1);

    gemm_mma_bf16x3<<<dim3(3*DD/128, BB*SS/128), 256, GSMEM_TOTAL>>>(b_qkv, 0, nullptr);

    attn_mma<<<dim3(SS/128, BB*HH), 256, AT_SMEM>>>();

    gemm_mma_bf16x3<<<dim3(DD/128, BB*SS/128), 256, GSMEM_TOTAL>>>(b_proj, 1, out);
}

// round 7
// speedup vs baseline: 6.5672x; 1.1855x over previous
#include <cuda_runtime.h>
#include <cuda_bf16.h>
#include <cstdint>

#define BB 4
#define SS 2048
#define DD 1024
#define HH 16
#define HD 64
#define SCALE 0.125f

// ---------------- scratch (__device__ globals; no allocs allowed) ----------
__device__ __nv_bfloat16 g_xh[BB*SS*DD];
__device__ __nv_bfloat16 g_xl[BB*SS*DD];
__device__ __nv_bfloat16 g_wqh[3*DD*DD];   // [N=3072, K=1024]  (W^T, K-major)
__device__ __nv_bfloat16 g_wql[3*DD*DD];
__device__ __nv_bfloat16 g_wph[DD*DD];     // [N=1024, K=1024]
__device__ __nv_bfloat16 g_wpl[DD*DD];
__device__ __nv_bfloat16 g_qh[BB*HH*SS*HD];   // Q (pre-scaled) [B,H,S,64]
__device__ __nv_bfloat16 g_ql[BB*HH*SS*HD];
__device__ __nv_bfloat16 g_kh[BB*HH*SS*HD];   // K [B,H,S,64]
__device__ __nv_bfloat16 g_kl[BB*HH*SS*HD];
__device__ __nv_bfloat16 g_vth[BB*HH*HD*SS];  // V^T [B,H,64,S]
__device__ __nv_bfloat16 g_vtl[BB*HH*HD*SS];
__device__ __nv_bfloat16 g_ch[BB*SS*DD];      // ctx hi
__device__ __nv_bfloat16 g_cl[BB*SS*DD];      // ctx lo

// ---------------- PTX helpers (sm_80-portable only) ------------------------
__device__ __forceinline__ uint32_t smem_u32(const void* p) {
    uint32_t a;
    asm("{ .reg .u64 t; cvta.to.shared.u64 t, %1; cvt.u32.u64 %0, t; }" : "=r"(a) : "l"(p));
    return a;
}
__device__ __forceinline__ void cp16(uint32_t s, const void* g) {
    asm volatile("cp.async.cg.shared.global [%0], [%1], 16;" :: "r"(s), "l"(g));
}
__device__ __forceinline__ void cp_commit() { asm volatile("cp.async.commit_group;"); }
template<int N> __device__ __forceinline__ void cp_wait() {
    asm volatile("cp.async.wait_group %0;" :: "n"(N));
}
__device__ __forceinline__ void ldsm4(uint32_t* r, uint32_t addr) {
    asm volatile("ldmatrix.sync.aligned.m8n8.x4.shared.b16 {%0,%1,%2,%3}, [%4];"
        : "=r"(r[0]), "=r"(r[1]), "=r"(r[2]), "=r"(r[3]) : "r"(addr));
}
__device__ __forceinline__ void mma16816(float* d, const uint32_t* a, const uint32_t* b) {
    asm volatile(
        "mma.sync.aligned.m16n8k16.row.col.f32.bf16.bf16.f32 "
        "{%0,%1,%2,%3}, {%4,%5,%6,%7}, {%8,%9}, {%0,%1,%2,%3};"
        : "+f"(d[0]), "+f"(d[1]), "+f"(d[2]), "+f"(d[3])
        : "r"(a[0]), "r"(a[1]), "r"(a[2]), "r"(a[3]), "r"(b[0]), "r"(b[1]));
}
// pack two f32 -> bf16x2 (first arg in low half)
__device__ __forceinline__ uint32_t packbf(float lo, float hi) {
    uint32_t r;
    asm("cvt.rn.bf16x2.f32 %0, %1, %2;" : "=r"(r) : "f"(hi), "f"(lo));
    return r;
}
__device__ __forceinline__ float bflo(uint32_t p) { return __uint_as_float(p << 16); }
__device__ __forceinline__ float bfhi(uint32_t p) { return __uint_as_float(p & 0xffff0000u); }

// ---------------- convert kernels ------------------------------------------
__global__ __launch_bounds__(256) void convert_split4(const float4* __restrict__ in, int n4)
{
    int i = blockIdx.x * 256 + threadIdx.x;
    if (i >= n4) return;
    float4 v = in[i];
    uint32_t h0 = packbf(v.x, v.y);
    uint32_t l0 = packbf(v.x - bflo(h0), v.y - bfhi(h0));
    uint32_t h1 = packbf(v.z, v.w);
    uint32_t l1 = packbf(v.z - bflo(h1), v.w - bfhi(h1));
    ((uint2*)g_xh)[i] = make_uint2(h0, h1);
    ((uint2*)g_xl)[i] = make_uint2(l0, l1);
}

// W[K,N] row-major -> T[N,K] hi/lo bf16.  which: 0 = qkv, 1 = proj
__global__ __launch_bounds__(256) void convert_transpose(
    const float* __restrict__ W, int K, int N, int which)
{
    __shared__ float t[32][33];
    __nv_bfloat16* Th = which ? g_wph : g_wqh;
    __nv_bfloat16* Tl = which ? g_wpl : g_wql;
    int n0 = blockIdx.x * 32, k0 = blockIdx.y * 32;
    int tx = threadIdx.x, ty = threadIdx.y;   // 32 x 8
#pragma unroll
    for (int j = 0; j < 4; j++)
        t[ty + j*8][tx] = W[(size_t)(k0 + ty + j*8) * N + n0 + tx];
    __syncthreads();
#pragma unroll
    for (int j = 0; j < 4; j++) {
        float v = t[tx][ty + j*8];
        __nv_bfloat16 h = __float2bfloat16(v);
        __nv_bfloat16 l = __float2bfloat16(v - __bfloat162float(h));
        size_t o = (size_t)(n0 + ty + j*8) * K + k0 + tx;
        Th[o] = h; Tl[o] = l;
    }
}

// ---------------- bf16x3 GEMM via mma.sync (HMMA) ---------------------------
// 3-stage cp.async, 64B swizzled rows, one __syncthreads per K-chunk.
#define G_PART  8192                    // 128 rows x 64B
#define G_STAGE (4 * G_PART)            // 32768
#define G_SMEM  (3 * G_STAGE)           // 98304

__global__ __launch_bounds__(256, 2) void gemm_mma_bf16x3(
    const float* __restrict__ bias, int mode, float* __restrict__ out)
{
    extern __shared__ char smem[];
    const uint32_t sb = smem_u32(smem);
    const int tid  = threadIdx.x;
    const int lane = tid & 31, warp = tid >> 5;
    const int wm = warp >> 1, wn = warp & 1;       // 4 x 2 warp grid
    const int m0 = blockIdx.y * 128, n0 = blockIdx.x * 128;

    const __nv_bfloat16* Ah = mode ? g_ch : g_xh;
    const __nv_bfloat16* Al = mode ? g_cl : g_xl;
    const __nv_bfloat16* Bh = mode ? g_wph : g_wqh;
    const __nv_bfloat16* Bl = mode ? g_wpl : g_wql;

    float d[64];
#pragma unroll
    for (int i = 0; i < 64; i++) d[i] = 0.f;

    // chunk c -> stage c%3; row*64 + 16*(u ^ ((row>>1)&3))
    auto load_chunk = [&](int c) {
        uint32_t st = sb + (uint32_t)(c % 3) * G_STAGE;
        int k0 = c * 32;
#pragma unroll
        for (int i = 0; i < 8; i++) {
            int id = i * 256 + tid;                  // 0..2047
            int part = id >> 9;                      // 0:Ah 1:Al 2:Bh 3:Bl
            int rem = id & 511;
            int row = rem >> 2, u = rem & 3;
            uint32_t dst = st + (uint32_t)part * G_PART + (uint32_t)row * 64
                         + (uint32_t)((u ^ ((row >> 1) & 3)) << 4);
            size_t go = (size_t)((part < 2 ? m0 : n0) + row) * 1024 + k0 + u * 8;
            const __nv_bfloat16* src =
                (part == 0) ? Ah : (part == 1) ? Al : (part == 2) ? Bh : Bl;
            cp16(dst, src + go);
        }
        cp_commit();
    };

    const int a_row0 = wm * 32 + (lane & 15);
    const int a_hi   = lane >> 4;                         // unit offset 0/1
    const int b_row0 = wn * 64 + (lane & 7) + ((lane & 16) ? 8 : 0);
    const int b_hi   = (lane & 8) ? 1 : 0;

    const int NCHUNK = 32;
    load_chunk(0); load_chunk(1);
    for (int c = 0; c < NCHUNK; c++) {
        if (c < NCHUNK - 1) cp_wait<1>(); else cp_wait<0>();
        __syncthreads();
        if (c + 2 < NCHUNK) load_chunk(c + 2);

        uint32_t st = sb + (uint32_t)(c % 3) * G_STAGE;
#pragma unroll
        for (int ks = 0; ks < 2; ks++) {
            uint32_t ah[2][4], al[2][4], bhf[4][4], blf[4][4];
#pragma unroll
            for (int mi = 0; mi < 2; mi++) {
                int row = a_row0 + mi * 16;
                int unit = ks * 2 + a_hi;
                uint32_t ro = (uint32_t)row * 64 + (uint32_t)((unit ^ ((row >> 1) & 3)) << 4);
                ldsm4(ah[mi], st + ro);
                ldsm4(al[mi], st + G_PART + ro);
            }
#pragma unroll
            for (int ni = 0; ni < 4; ni++) {
                int row = b_row0 + ni * 16;
                int unit = ks * 2 + b_hi;
                uint32_t ro = (uint32_t)row * 64 + (uint32_t)((unit ^ ((row >> 1) & 3)) << 4);
                ldsm4(bhf[ni], st + 2 * G_PART + ro);
                ldsm4(blf[ni], st + 3 * G_PART + ro);
            }
#pragma unroll
            for (int mi = 0; mi < 2; mi++)
#pragma unroll
                for (int nb = 0; nb < 8; nb++) {
                    float* dp = d + (mi * 8 + nb) * 4;
                    const uint32_t* bph = &bhf[nb >> 1][(nb & 1) * 2];
                    const uint32_t* bpl = &blf[nb >> 1][(nb & 1) * 2];
                    mma16816(dp, ah[mi], bph);
                    mma16816(dp, al[mi], bph);
                    mma16816(dp, ah[mi], bpl);
                }
        }
    }

    // ---- epilogue --------------------------------------------------------
    const int r = lane >> 2, cpair = (lane & 3) * 2;
    const int three = n0 >> 10, rem0 = n0 & 1023;

#pragma unroll
    for (int mi = 0; mi < 2; mi++)
#pragma unroll
        for (int nb = 0; nb < 8; nb++) {
            float* dp = d + (mi * 8 + nb) * 4;
            int m_top = m0 + wm * 32 + mi * 16 + r;
            int nofs = wn * 64 + nb * 8 + cpair;
            int n = n0 + nofs;
            float bx = __ldg(bias + n), by = __ldg(bias + n + 1);
            float v00 = dp[0] + bx, v01 = dp[1] + by;   // row m_top
            float v10 = dp[2] + bx, v11 = dp[3] + by;   // row m_top+8
            if (mode == 1) {
                *(float2*)(out + (size_t)m_top * 1024 + n) = make_float2(v00, v01);
                *(float2*)(out + (size_t)(m_top + 8) * 1024 + n) = make_float2(v10, v11);
                continue;
            }
            int nrem = rem0 + nofs;
            int h = nrem >> 6, dd2 = nrem & 63;
            int bh0 = (m_top >> 11) * HH + h;           int s0 = m_top & 2047;
            int bh1 = ((m_top + 8) >> 11) * HH + h;     int s1 = (m_top + 8) & 2047;
            if (three == 2) {
                uint32_t H0 = packbf(v00, v01), L0 = packbf(v00 - bflo(H0), v01 - bfhi(H0));
                uint32_t H1 = packbf(v10, v11), L1 = packbf(v10 - bflo(H1), v11 - bfhi(H1));
                size_t r0 = ((size_t)bh0 * HD + dd2) * SS;
                size_t r1 = ((size_t)bh1 * HD + dd2) * SS;
                g_vth[r0 + s0]      = __ushort_as_bfloat16((unsigned short)(H0 & 0xffff));
                g_vth[r0 + SS + s0] = __ushort_as_bfloat16((unsigned short)(H0 >> 16));
                g_vtl[r0 + s0]      = __ushort_as_bfloat16((unsigned short)(L0 & 0xffff));
                g_vtl[r0 + SS + s0] = __ushort_as_bfloat16((unsigned short)(L0 >> 16));
                g_vth[r1 + s1]      = __ushort_as_bfloat16((unsigned short)(H1 & 0xffff));
                g_vth[r1 + SS + s1] = __ushort_as_bfloat16((unsigned short)(H1 >> 16));
                g_vtl[r1 + s1]      = __ushort_as_bfloat16((unsigned short)(L1 & 0xffff));
                g_vtl[r1 + SS + s1] = __ushort_as_bfloat16((unsigned short)(L1 >> 16));
            } else {
                __nv_bfloat16 *Hdst, *Ldst;
                if (three == 0) { v00 *= SCALE; v01 *= SCALE; v10 *= SCALE; v11 *= SCALE;
                                  Hdst = g_qh; Ldst = g_ql; }
                else            { Hdst = g_kh; Ldst = g_kl; }
                uint32_t H0 = packbf(v00, v01), L0 = packbf(v00 - bflo(H0), v01 - bfhi(H0));
                uint32_t H1 = packbf(v10, v11), L1 = packbf(v10 - bflo(H1), v11 - bfhi(H1));
                size_t i0 = ((size_t)bh0 * SS + s0) * HD + dd2;
                size_t i1 = ((size_t)bh1 * SS + s1) * HD + dd2;
                *(uint32_t*)(Hdst + i0) = H0;  *(uint32_t*)(Ldst + i0) = L0;
                *(uint32_t*)(Hdst + i1) = H1;  *(uint32_t*)(Ldst + i1) = L1;
            }
        }
}

// ---------------- flash attention via mma.sync ------------------------------
// 2-stage swizzled K/V tiles (64KB) + persistent swizzled Q (32KB) = 96KB.
// Qh frags resident in regs; Ql frags reloaded per tile (keeps regs <= 128).
#define A_BUF   8192                    // 64 rows x 128B, SW128 swizzle
#define A_STAGE (4 * A_BUF)             // 32768
#define A_QOFF  (2 * A_STAGE)           // 65536
#define A_SMEM  (A_QOFF + 2 * 16384)    // 98304

__global__ __launch_bounds__(256, 2) void attn_mma()
{
    extern __shared__ char smem[];
    const uint32_t sb = smem_u32(smem);
    const int tid = threadIdx.x;
    const int lane = tid & 31, w = tid >> 5;
    const int bh = blockIdx.y;
    const int q0 = blockIdx.x * 128;

    const __nv_bfloat16* Kh = g_kh + (size_t)bh * SS * HD;
    const __nv_bfloat16* Kl = g_kl + (size_t)bh * SS * HD;
    const __nv_bfloat16* Vth = g_vth + (size_t)bh * HD * SS;
    const __nv_bfloat16* Vtl = g_vtl + (size_t)bh * HD * SS;

    // ---- load Q (hi+lo) into persistent swizzled area --------------------
    {
        const __nv_bfloat16* Qh = g_qh + ((size_t)bh * SS + q0) * HD;
        const __nv_bfloat16* Ql = g_ql + ((size_t)bh * SS + q0) * HD;
#pragma unroll
        for (int i = 0; i < 8; i++) {
            int id = i * 256 + tid;                  // 0..2047
            int buf = id >> 10;                      // 0=hi 1=lo
            int rem = id & 1023;
            int row = rem >> 3, u = rem & 7;
            uint32_t dst = sb + A_QOFF + (uint32_t)buf * 16384
                         + (uint32_t)row * 128 + (uint32_t)((u ^ (row & 7)) << 4);
            const __nv_bfloat16* src = buf ? Ql : Qh;
            cp16(dst, src + (size_t)row * HD + u * 8);
        }
        cp_commit();
    }

    const int a_row = w * 16 + (lane & 15);
    const int a_hi  = lane >> 4;
    const int b_row_off = (lane & 7) + ((lane & 16) ? 8 : 0);
    const int b_hi  = (lane & 8) ? 1 : 0;

    cp_wait<0>();
    __syncthreads();

    uint32_t qh[4][4];
#pragma unroll
    for (int kc = 0; kc < 4; kc++) {
        int unit = kc * 2 + a_hi;
        uint32_t ro = (uint32_t)a_row * 128 + (uint32_t)((unit ^ (a_row & 7)) << 4);
        ldsm4(qh[kc], sb + A_QOFF + ro);
    }

    // ---- kv tile loader (SW128 swizzle) ----------------------------------
    auto load_tile = [&](int t) {
        int kv0 = t * 64;
        uint32_t st = sb + (uint32_t)(t & 1) * A_STAGE;
#pragma unroll
        for (int i = 0; i < 8; i++) {
            int id = i * 256 + tid;                  // 0..2047
            int buf = id >> 9;                       // 0:Kh 1:Kl 2:Vth 3:Vtl
            int rem = id & 511;
            int row = rem >> 3, u = rem & 7;
            uint32_t dst = st + (uint32_t)buf * A_BUF
                         + (uint32_t)row * 128 + (uint32_t)((u ^ (row & 7)) << 4);
            const void* src;
            if (buf < 2) {
                const __nv_bfloat16* p = buf ? Kl : Kh;
                src = p + ((size_t)(kv0 + row)) * HD + u * 8;
            } else {
                const __nv_bfloat16* p = (buf == 2) ? Vth : Vtl;
                src = p + (size_t)row * SS + kv0 + u * 8;
            }
            cp16(dst, src);
        }
        cp_commit();
    };

    float o[8][4];
#pragma unroll
    for (int j = 0; j < 8; j++)
#pragma unroll
        for (int k = 0; k < 4; k++) o[j][k] = 0.f;
    float m0 = -1e30f, m1 = -1e30f, l0 = 0.f, l1 = 0.f;

    load_tile(0);
    for (int t = 0; t < SS / 64; t++) {
        if (t + 1 < SS / 64) { load_tile(t + 1); cp_wait<1>(); }
        else                 { cp_wait<0>(); }
        __syncthreads();

        uint32_t st = sb + (uint32_t)(t & 1) * A_STAGE;

        // ---- S = Q K^T (bf16x3) -----------------------------------------
        float s[8][4];
#pragma unroll
        for (int j = 0; j < 8; j++)
#pragma unroll
            for (int k = 0; k < 4; k++) s[j][k] = 0.f;

#pragma unroll
        for (int kc = 0; kc < 4; kc++) {
            uint32_t ql4[4];
            {
                int unit = kc * 2 + a_hi;
                uint32_t ro = (uint32_t)a_row * 128 + (uint32_t)((unit ^ (a_row & 7)) << 4);
                ldsm4(ql4, sb + A_QOFF + 16384 + ro);
            }
#pragma unroll
            for (int ni = 0; ni < 4; ni++) {
                int row = ni * 16 + b_row_off;
                int unit = kc * 2 + b_hi;
                uint32_t ro = (uint32_t)row * 128 + (uint32_t)((unit ^ (row & 7)) << 4);
                uint32_t bh4[4], bl4[4];
                ldsm4(bh4, st + ro);
                ldsm4(bl4, st + A_BUF + ro);
#pragma unroll
                for (int hf = 0; hf < 2; hf++) {
                    float* sp = s[ni * 2 + hf];
                    mma16816(sp, qh[kc], &bh4[hf * 2]);
                    mma16816(sp, ql4,    &bh4[hf * 2]);
                    mma16816(sp, qh[kc], &bl4[hf * 2]);
                }
            }
        }

        // ---- online softmax (rows owned by quad lanes) -------------------
        float mx0 = s[0][0], mx1 = s[0][2];
#pragma unroll
        for (int j = 0; j < 8; j++) {
            mx0 = fmaxf(mx0, fmaxf(s[j][0], s[j][1]));
            mx1 = fmaxf(mx1, fmaxf(s[j][2], s[j][3]));
        }
        mx0 = fmaxf(mx0, __shfl_xor_sync(0xffffffffu, mx0, 1));
        mx0 = fmaxf(mx0, __shfl_xor_sync(0xffffffffu, mx0, 2));
        mx1 = fmaxf(mx1, __shfl_xor_sync(0xffffffffu, mx1, 1));
        mx1 = fmaxf(mx1, __shfl_xor_sync(0xffffffffu, mx1, 2));
        float mn0 = fmaxf(m0, mx0), mn1 = fmaxf(m1, mx1);
        float al0 = __expf(m0 - mn0), al1 = __expf(m1 - mn1);
        float sum0 = 0.f, sum1 = 0.f;
#pragma unroll
        for (int j = 0; j < 8; j++) {
            s[j][0] = __expf(s[j][0] - mn0); sum0 += s[j][0];
            s[j][1] = __expf(s[j][1] - mn0); sum0 += s[j][1];
            s[j][2] = __expf(s[j][2] - mn1); sum1 += s[j][2];
            s[j][3] = __expf(s[j][3] - mn1); sum1 += s[j][3];
        }
        sum0 += __shfl_xor_sync(0xffffffffu, sum0, 1);
        sum0 += __shfl_xor_sync(0xffffffffu, sum0, 2);
        sum1 += __shfl_xor_sync(0xffffffffu, sum1, 1);
        sum1 += __shfl_xor_sync(0xffffffffu, sum1, 2);
        l0 = l0 * al0 + sum0; l1 = l1 * al1 + sum1;
        m0 = mn0; m1 = mn1;
#pragma unroll
        for (int j = 0; j < 8; j++) {
            o[j][0] *= al0; o[j][1] *= al0;
            o[j][2] *= al1; o[j][3] *= al1;
        }

        // ---- O += P V (bf16x3), A-frags repacked from S accum ------------
#pragma unroll
        for (int kvc = 0; kvc < 4; kvc++) {
            uint32_t ah4[4], al4[4];
            {
                float* p0 = s[kvc * 2];
                float* p1 = s[kvc * 2 + 1];
                ah4[0] = packbf(p0[0], p0[1]);
                al4[0] = packbf(p0[0] - bflo(ah4[0]), p0[1] - bfhi(ah4[0]));
                ah4[1] = packbf(p0[2], p0[3]);
                al4[1] = packbf(p0[2] - bflo(ah4[1]), p0[3] - bfhi(ah4[1]));
                ah4[2] = packbf(p1[0], p1[1]);
                al4[2] = packbf(p1[0] - bflo(ah4[2]), p1[1] - bfhi(ah4[2]));
                ah4[3] = packbf(p1[2], p1[3]);
                al4[3] = packbf(p1[2] - bflo(ah4[3]), p1[3] - bfhi(ah4[3]));
            }
#pragma unroll
            for (int ni = 0; ni < 4; ni++) {
                int row = ni * 16 + b_row_off;
                int unit = kvc * 2 + b_hi;
                uint32_t ro = (uint32_t)row * 128 + (uint32_t)((unit ^ (row & 7)) << 4);
                uint32_t bh4[4], bl4[4];
                ldsm4(bh4, st + 2 * A_BUF + ro);
                ldsm4(bl4, st + 3 * A_BUF + ro);
#pragma unroll
                for (int hf = 0; hf < 2; hf++) {
                    float* op = o[ni * 2 + hf];
                    mma16816(op, ah4, &bh4[hf * 2]);
                    mma16816(op, al4, &bh4[hf * 2]);
                    mma16816(op, ah4, &bl4[hf * 2]);
                }
            }
        }
        __syncthreads();
    }

    // ---- write ctx hi/lo --------------------------------------------------
    const int r = lane >> 2, cpair = (lane & 3) * 2;
    const int b = bh >> 4, h = bh & 15;
    float inv0 = 1.f / l0, inv1 = 1.f / l1;
    int row0 = q0 + w * 16 + r, row1 = row0 + 8;
#pragma unroll
    for (int j = 0; j < 8; j++) {
        int col = h * HD + j * 8 + cpair;
        float v00 = o[j][0] * inv0, v01 = o[j][1] * inv0;
        float v10 = o[j][2] * inv1, v11 = o[j][3] * inv1;
        uint32_t H0 = packbf(v00, v01), L0 = packbf(v00 - bflo(H0), v01 - bfhi(H0));
        uint32_t H1 = packbf(v10, v11), L1 = packbf(v10 - bflo(H1), v11 - bfhi(H1));
        size_t i0 = ((size_t)b * SS + row0) * DD + col;
        size_t i1 = ((size_t)b * SS + row1) * DD + col;
        *(uint32_t*)(g_ch + i0) = H0;  *(uint32_t*)(g_cl + i0) = L0;
        *(uint32_t*)(g_ch + i1) = H1;  *(uint32_t*)(g_cl + i1) = L1;
    }
}

// ---------------------------------------------------------------------------
extern "C" void kernel_launch(void* const* d_in, const int* in_sizes, int n_in,
                              void* d_out, int out_size)
{
    const float* x      = (const float*)d_in[0];
    const float* w_qkv  = (const float*)d_in[1];
    const float* b_qkv  = (const float*)d_in[2];
    const float* w_proj = (const float*)d_in[3];
    const float* b_proj = (const float*)d_in[4];
    float* out = (float*)d_out;

    cudaFuncSetAttribute(gemm_mma_bf16x3,
                         cudaFuncAttributeMaxDynamicSharedMemorySize, G_SMEM);
    cudaFuncSetAttribute(attn_mma,
                         cudaFuncAttributeMaxDynamicSharedMemorySize, A_SMEM);

    int nx4 = BB*SS*DD/4;
    convert_split4<<<(nx4 + 255)/256, 256>>>((const float4*)x, nx4);
    convert_transpose<<<dim3(3*DD/32, DD/32), dim3(32, 8)>>>(w_qkv, DD, 3*DD, 0);
    convert_transpose<<<dim3(DD/32, DD/32), dim3(32, 8)>>>(w_proj, DD, DD, 1);

    gemm_mma_bf16x3<<<dim3(3*DD/128, BB*SS/128), 256, G_SMEM>>>(b_qkv, 0, nullptr);

    attn_mma<<<dim3(SS/128, BB*HH), 256, A_SMEM>>>();

    gemm_mma_bf16x3<<<dim3(DD/128, BB*SS/128), 256, G_SMEM>>>(b_proj, 1, out);
}

// round 8
// speedup vs baseline: 9.1553x; 1.3941x over previous
#include <cuda_runtime.h>
#include <cuda_fp16.h>
#include <cstdint>

#define BB 4
#define SS 2048
#define DD 1024
#define HH 16
#define HD 64
#define SCALE 0.125f

// ---------------- scratch (__device__ globals; no allocs allowed) ----------
__device__ __half g_xh[BB*SS*DD];
__device__ __half g_xl[BB*SS*DD];
__device__ __half g_wq[3*DD*DD];      // W_qkv^T [3072,1024], fp16-rounded
__device__ __half g_wp[DD*DD];        // W_proj^T [1024,1024], fp16-rounded
__device__ __half g_qh[BB*HH*SS*HD];  // Q (pre-scaled) hi [B,H,S,64]
__device__ __half g_ql[BB*HH*SS*HD];  // Q lo
__device__ __half g_kh[BB*HH*SS*HD];  // K (fp16-rounded) [B,H,S,64]
__device__ __half g_vt[BB*HH*HD*SS];  // V^T (fp16-rounded) [B,H,64,S]
__device__ __half g_ch[BB*SS*DD];     // ctx hi
__device__ __half g_cl[BB*SS*DD];     // ctx lo

// ---------------- PTX helpers (sm_80-portable only) ------------------------
__device__ __forceinline__ uint32_t smem_u32(const void* p) {
    uint32_t a;
    asm("{ .reg .u64 t; cvta.to.shared.u64 t, %1; cvt.u32.u64 %0, t; }" : "=r"(a) : "l"(p));
    return a;
}
__device__ __forceinline__ void cp16(uint32_t s, const void* g) {
    asm volatile("cp.async.cg.shared.global [%0], [%1], 16;" :: "r"(s), "l"(g));
}
__device__ __forceinline__ void cp_commit() { asm volatile("cp.async.commit_group;"); }
template<int N> __device__ __forceinline__ void cp_wait() {
    asm volatile("cp.async.wait_group %0;" :: "n"(N));
}
__device__ __forceinline__ void ldsm4(uint32_t* r, uint32_t addr) {
    asm volatile("ldmatrix.sync.aligned.m8n8.x4.shared.b16 {%0,%1,%2,%3}, [%4];"
        : "=r"(r[0]), "=r"(r[1]), "=r"(r[2]), "=r"(r[3]) : "r"(addr));
}
__device__ __forceinline__ void mma16816(float* d, const uint32_t* a, const uint32_t* b) {
    asm volatile(
        "mma.sync.aligned.m16n8k16.row.col.f32.f16.f16.f32 "
        "{%0,%1,%2,%3}, {%4,%5,%6,%7}, {%8,%9}, {%0,%1,%2,%3};"
        : "+f"(d[0]), "+f"(d[1]), "+f"(d[2]), "+f"(d[3])
        : "r"(a[0]), "r"(a[1]), "r"(a[2]), "r"(a[3]), "r"(b[0]), "r"(b[1]));
}
// pack two f32 -> f16x2 (first arg in low half)
__device__ __forceinline__ uint32_t packh(float lo, float hi) {
    uint32_t r;
    asm("cvt.rn.f16x2.f32 %0, %1, %2;" : "=r"(r) : "f"(hi), "f"(lo));
    return r;
}
__device__ __forceinline__ float h_lo(uint32_t p) {
    return __half2float(__ushort_as_half((unsigned short)(p & 0xffff)));
}
__device__ __forceinline__ float h_hi(uint32_t p) {
    return __half2float(__ushort_as_half((unsigned short)(p >> 16)));
}

// ---------------- convert kernels ------------------------------------------
__global__ __launch_bounds__(256) void convert_split4(const float4* __restrict__ in, int n4)
{
    int i = blockIdx.x * 256 + threadIdx.x;
    if (i >= n4) return;
    float4 v = in[i];
    uint32_t h0 = packh(v.x, v.y);
    uint32_t l0 = packh(v.x - h_lo(h0), v.y - h_hi(h0));
    uint32_t h1 = packh(v.z, v.w);
    uint32_t l1 = packh(v.z - h_lo(h1), v.w - h_hi(h1));
    ((uint2*)g_xh)[i] = make_uint2(h0, h1);
    ((uint2*)g_xl)[i] = make_uint2(l0, l1);
}

// W[K,N] row-major -> T[N,K] fp16 (rounded).  which: 0 = qkv, 1 = proj
__global__ __launch_bounds__(256) void convert_transpose(
    const float* __restrict__ W, int K, int N, int which)
{
    __shared__ float t[32][33];
    __half* T = which ? g_wp : g_wq;
    int n0 = blockIdx.x * 32, k0 = blockIdx.y * 32;
    int tx = threadIdx.x, ty = threadIdx.y;   // 32 x 8
#pragma unroll
    for (int j = 0; j < 4; j++)
        t[ty + j*8][tx] = W[(size_t)(k0 + ty + j*8) * N + n0 + tx];
    __syncthreads();
#pragma unroll
    for (int j = 0; j < 4; j++) {
        float v = t[tx][ty + j*8];
        T[(size_t)(n0 + ty + j*8) * K + k0 + tx] = __float2half(v);
    }
}

// ---------------- fp16x2 GEMM via mma.sync (HMMA) ---------------------------
// 3 parts per stage (Ah, Al, Bh), 64B swizzled rows, 3-stage cp.async.
#define G_PART  8192                    // 128 rows x 64B
#define G_STAGE (3 * G_PART)            // 24576
#define G_SMEM  (3 * G_STAGE)           // 73728

__global__ __launch_bounds__(256, 2) void gemm_mma_f16x2(
    const float* __restrict__ bias, int mode, float* __restrict__ out)
{
    extern __shared__ char smem[];
    const uint32_t sb = smem_u32(smem);
    const int tid  = threadIdx.x;
    const int lane = tid & 31, warp = tid >> 5;
    const int wm = warp >> 1, wn = warp & 1;       // 4 x 2 warp grid
    const int m0 = blockIdx.y * 128, n0 = blockIdx.x * 128;

    const __half* Ah = mode ? g_ch : g_xh;
    const __half* Al = mode ? g_cl : g_xl;
    const __half* Bh = mode ? g_wp : g_wq;

    float d[64];
#pragma unroll
    for (int i = 0; i < 64; i++) d[i] = 0.f;

    // chunk c -> stage c%3; row*64 + 16*(u ^ ((row>>1)&3))
    auto load_chunk = [&](int c) {
        uint32_t st = sb + (uint32_t)(c % 3) * G_STAGE;
        int k0 = c * 32;
#pragma unroll
        for (int i = 0; i < 6; i++) {
            int id = i * 256 + tid;                  // 0..1535
            int part = id >> 9;                      // 0:Ah 1:Al 2:Bh
            int rem = id & 511;
            int row = rem >> 2, u = rem & 3;
            uint32_t dst = st + (uint32_t)part * G_PART + (uint32_t)row * 64
                         + (uint32_t)((u ^ ((row >> 1) & 3)) << 4);
            size_t go = (size_t)((part < 2 ? m0 : n0) + row) * 1024 + k0 + u * 8;
            const __half* src = (part == 0) ? Ah : (part == 1) ? Al : Bh;
            cp16(dst, src + go);
        }
        cp_commit();
    };

    const int a_row0 = wm * 32 + (lane & 15);
    const int a_hi   = lane >> 4;                         // unit offset 0/1
    const int b_row0 = wn * 64 + (lane & 7) + ((lane & 16) ? 8 : 0);
    const int b_hi   = (lane & 8) ? 1 : 0;

    const int NCHUNK = 32;
    load_chunk(0); load_chunk(1);
    for (int c = 0; c < NCHUNK; c++) {
        if (c < NCHUNK - 1) cp_wait<1>(); else cp_wait<0>();
        __syncthreads();
        if (c + 2 < NCHUNK) load_chunk(c + 2);

        uint32_t st = sb + (uint32_t)(c % 3) * G_STAGE;
#pragma unroll
        for (int ks = 0; ks < 2; ks++) {
            uint32_t ah[2][4], al[2][4], bhf[4][4];
#pragma unroll
            for (int mi = 0; mi < 2; mi++) {
                int row = a_row0 + mi * 16;
                int unit = ks * 2 + a_hi;
                uint32_t ro = (uint32_t)row * 64 + (uint32_t)((unit ^ ((row >> 1) & 3)) << 4);
                ldsm4(ah[mi], st + ro);
                ldsm4(al[mi], st + G_PART + ro);
            }
#pragma unroll
            for (int ni = 0; ni < 4; ni++) {
                int row = b_row0 + ni * 16;
                int unit = ks * 2 + b_hi;
                uint32_t ro = (uint32_t)row * 64 + (uint32_t)((unit ^ ((row >> 1) & 3)) << 4);
                ldsm4(bhf[ni], st + 2 * G_PART + ro);
            }
#pragma unroll
            for (int mi = 0; mi < 2; mi++)
#pragma unroll
                for (int nb = 0; nb < 8; nb++) {
                    float* dp = d + (mi * 8 + nb) * 4;
                    const uint32_t* bph = &bhf[nb >> 1][(nb & 1) * 2];
                    mma16816(dp, ah[mi], bph);
                    mma16816(dp, al[mi], bph);
                }
        }
    }

    // ---- epilogue --------------------------------------------------------
    const int r = lane >> 2, cpair = (lane & 3) * 2;
    const int three = n0 >> 10, rem0 = n0 & 1023;

#pragma unroll
    for (int mi = 0; mi < 2; mi++)
#pragma unroll
        for (int nb = 0; nb < 8; nb++) {
            float* dp = d + (mi * 8 + nb) * 4;
            int m_top = m0 + wm * 32 + mi * 16 + r;
            int nofs = wn * 64 + nb * 8 + cpair;
            int n = n0 + nofs;
            float bx = __ldg(bias + n), by = __ldg(bias + n + 1);
            float v00 = dp[0] + bx, v01 = dp[1] + by;   // row m_top
            float v10 = dp[2] + bx, v11 = dp[3] + by;   // row m_top+8
            if (mode == 1) {
                *(float2*)(out + (size_t)m_top * 1024 + n) = make_float2(v00, v01);
                *(float2*)(out + (size_t)(m_top + 8) * 1024 + n) = make_float2(v10, v11);
                continue;
            }
            int nrem = rem0 + nofs;
            int h = nrem >> 6, dd2 = nrem & 63;
            int bh0 = (m_top >> 11) * HH + h;           int s0 = m_top & 2047;
            int bh1 = ((m_top + 8) >> 11) * HH + h;     int s1 = (m_top + 8) & 2047;
            if (three == 2) {
                // V: transposed store [B,H,64,S], fp16-rounded
                size_t r0 = ((size_t)bh0 * HD + dd2) * SS;
                size_t r1 = ((size_t)bh1 * HD + dd2) * SS;
                g_vt[r0 + s0]      = __float2half(v00);
                g_vt[r0 + SS + s0] = __float2half(v01);
                g_vt[r1 + s1]      = __float2half(v10);
                g_vt[r1 + SS + s1] = __float2half(v11);
            } else if (three == 1) {
                // K: fp16-rounded
                size_t i0 = ((size_t)bh0 * SS + s0) * HD + dd2;
                size_t i1 = ((size_t)bh1 * SS + s1) * HD + dd2;
                *(uint32_t*)(g_kh + i0) = packh(v00, v01);
                *(uint32_t*)(g_kh + i1) = packh(v10, v11);
            } else {
                // Q: scaled, split hi/lo
                v00 *= SCALE; v01 *= SCALE; v10 *= SCALE; v11 *= SCALE;
                uint32_t H0 = packh(v00, v01), L0 = packh(v00 - h_lo(H0), v01 - h_hi(H0));
                uint32_t H1 = packh(v10, v11), L1 = packh(v10 - h_lo(H1), v11 - h_hi(H1));
                size_t i0 = ((size_t)bh0 * SS + s0) * HD + dd2;
                size_t i1 = ((size_t)bh1 * SS + s1) * HD + dd2;
                *(uint32_t*)(g_qh + i0) = H0;  *(uint32_t*)(g_ql + i0) = L0;
                *(uint32_t*)(g_qh + i1) = H1;  *(uint32_t*)(g_ql + i1) = L1;
            }
        }
}

// ---------------- flash attention via mma.sync (fp16x2) ---------------------
// 2-stage K/V tiles (Kh,Vt: 16KB/stage) + persistent Q hi/lo (32KB) = 64KB.
#define A_BUF   8192                    // 64 rows x 128B, SW128 swizzle
#define A_STAGE (2 * A_BUF)             // 16384
#define A_QOFF  (2 * A_STAGE)           // 32768
#define A_SMEM  (A_QOFF + 2 * 16384)    // 65536

__global__ __launch_bounds__(256, 2) void attn_mma()
{
    extern __shared__ char smem[];
    const uint32_t sb = smem_u32(smem);
    const int tid = threadIdx.x;
    const int lane = tid & 31, w = tid >> 5;
    const int bh = blockIdx.y;
    const int q0 = blockIdx.x * 128;

    const __half* Kh = g_kh + (size_t)bh * SS * HD;
    const __half* Vt = g_vt + (size_t)bh * HD * SS;

    // ---- load Q (hi+lo) into persistent swizzled area --------------------
    {
        const __half* Qh = g_qh + ((size_t)bh * SS + q0) * HD;
        const __half* Ql = g_ql + ((size_t)bh * SS + q0) * HD;
#pragma unroll
        for (int i = 0; i < 8; i++) {
            int id = i * 256 + tid;                  // 0..2047
            int buf = id >> 10;                      // 0=hi 1=lo
            int rem = id & 1023;
            int row = rem >> 3, u = rem & 7;
            uint32_t dst = sb + A_QOFF + (uint32_t)buf * 16384
                         + (uint32_t)row * 128 + (uint32_t)((u ^ (row & 7)) << 4);
            const __half* src = buf ? Ql : Qh;
            cp16(dst, src + (size_t)row * HD + u * 8);
        }
        cp_commit();
    }

    const int a_row = w * 16 + (lane & 15);
    const int a_hi  = lane >> 4;
    const int b_row_off = (lane & 7) + ((lane & 16) ? 8 : 0);
    const int b_hi  = (lane & 8) ? 1 : 0;

    cp_wait<0>();
    __syncthreads();

    uint32_t qh[4][4];
#pragma unroll
    for (int kc = 0; kc < 4; kc++) {
        int unit = kc * 2 + a_hi;
        uint32_t ro = (uint32_t)a_row * 128 + (uint32_t)((unit ^ (a_row & 7)) << 4);
        ldsm4(qh[kc], sb + A_QOFF + ro);
    }

    // ---- kv tile loader (SW128 swizzle) ----------------------------------
    auto load_tile = [&](int t) {
        int kv0 = t * 64;
        uint32_t st = sb + (uint32_t)(t & 1) * A_STAGE;
#pragma unroll
        for (int i = 0; i < 4; i++) {
            int id = i * 256 + tid;                  // 0..1023
            int buf = id >> 9;                       // 0:Kh 1:Vt
            int rem = id & 511;
            int row = rem >> 3, u = rem & 7;
            uint32_t dst = st + (uint32_t)buf * A_BUF
                         + (uint32_t)row * 128 + (uint32_t)((u ^ (row & 7)) << 4);
            const void* src;
            if (buf == 0) src = Kh + ((size_t)(kv0 + row)) * HD + u * 8;
            else          src = Vt + (size_t)row * SS + kv0 + u * 8;
            cp16(dst, src);
        }
        cp_commit();
    };

    float o[8][4];
#pragma unroll
    for (int j = 0; j < 8; j++)
#pragma unroll
        for (int k = 0; k < 4; k++) o[j][k] = 0.f;
    float m0 = -1e30f, m1 = -1e30f, l0 = 0.f, l1 = 0.f;

    load_tile(0);
    for (int t = 0; t < SS / 64; t++) {
        if (t + 1 < SS / 64) { load_tile(t + 1); cp_wait<1>(); }
        else                 { cp_wait<0>(); }
        __syncthreads();

        uint32_t st = sb + (uint32_t)(t & 1) * A_STAGE;

        // ---- S = Q K^T (fp16x2: Qh+Ql vs rounded K) ----------------------
        float s[8][4];
#pragma unroll
        for (int j = 0; j < 8; j++)
#pragma unroll
            for (int k = 0; k < 4; k++) s[j][k] = 0.f;

#pragma unroll
        for (int kc = 0; kc < 4; kc++) {
            uint32_t ql4[4];
            {
                int unit = kc * 2 + a_hi;
                uint32_t ro = (uint32_t)a_row * 128 + (uint32_t)((unit ^ (a_row & 7)) << 4);
                ldsm4(ql4, sb + A_QOFF + 16384 + ro);
            }
#pragma unroll
            for (int ni = 0; ni < 4; ni++) {
                int row = ni * 16 + b_row_off;
                int unit = kc * 2 + b_hi;
                uint32_t ro = (uint32_t)row * 128 + (uint32_t)((unit ^ (row & 7)) << 4);
                uint32_t bh4[4];
                ldsm4(bh4, st + ro);
#pragma unroll
                for (int hf = 0; hf < 2; hf++) {
                    float* sp = s[ni * 2 + hf];
                    mma16816(sp, qh[kc], &bh4[hf * 2]);
                    mma16816(sp, ql4,    &bh4[hf * 2]);
                }
            }
        }

        // ---- online softmax (rows owned by quad lanes) -------------------
        float mx0 = s[0][0], mx1 = s[0][2];
#pragma unroll
        for (int j = 0; j < 8; j++) {
            mx0 = fmaxf(mx0, fmaxf(s[j][0], s[j][1]));
            mx1 = fmaxf(mx1, fmaxf(s[j][2], s[j][3]));
        }
        mx0 = fmaxf(mx0, __shfl_xor_sync(0xffffffffu, mx0, 1));
        mx0 = fmaxf(mx0, __shfl_xor_sync(0xffffffffu, mx0, 2));
        mx1 = fmaxf(mx1, __shfl_xor_sync(0xffffffffu, mx1, 1));
        mx1 = fmaxf(mx1, __shfl_xor_sync(0xffffffffu, mx1, 2));
        float mn0 = fmaxf(m0, mx0), mn1 = fmaxf(m1, mx1);
        float al0 = __expf(m0 - mn0), al1 = __expf(m1 - mn1);
        float sum0 = 0.f, sum1 = 0.f;
#pragma unroll
        for (int j = 0; j < 8; j++) {
            s[j][0] = __expf(s[j][0] - mn0); sum0 += s[j][0];
            s[j][1] = __expf(s[j][1] - mn0); sum0 += s[j][1];
            s[j][2] = __expf(s[j][2] - mn1); sum1 += s[j][2];
            s[j][3] = __expf(s[j][3] - mn1); sum1 += s[j][3];
        }
        sum0 += __shfl_xor_sync(0xffffffffu, sum0, 1);
        sum0 += __shfl_xor_sync(0xffffffffu, sum0, 2);
        sum1 += __shfl_xor_sync(0xffffffffu, sum1, 1);
        sum1 += __shfl_xor_sync(0xffffffffu, sum1, 2);
        l0 = l0 * al0 + sum0; l1 = l1 * al1 + sum1;
        m0 = mn0; m1 = mn1;
#pragma unroll
        for (int j = 0; j < 8; j++) {
            o[j][0] *= al0; o[j][1] *= al0;
            o[j][2] *= al1; o[j][3] *= al1;
        }

        // ---- O += P V (fp16x2: Ph+Pl vs rounded V) -----------------------
#pragma unroll
        for (int kvc = 0; kvc < 4; kvc++) {
            uint32_t ph4[4], pl4[4];
            {
                float* p0 = s[kvc * 2];
                float* p1 = s[kvc * 2 + 1];
                ph4[0] = packh(p0[0], p0[1]);
                pl4[0] = packh(p0[0] - h_lo(ph4[0]), p0[1] - h_hi(ph4[0]));
                ph4[1] = packh(p0[2], p0[3]);
                pl4[1] = packh(p0[2] - h_lo(ph4[1]), p0[3] - h_hi(ph4[1]));
                ph4[2] = packh(p1[0], p1[1]);
                pl4[2] = packh(p1[0] - h_lo(ph4[2]), p1[1] - h_hi(ph4[2]));
                ph4[3] = packh(p1[2], p1[3]);
                pl4[3] = packh(p1[2] - h_lo(ph4[3]), p1[3] - h_hi(ph4[3]));
            }
#pragma unroll
            for (int ni = 0; ni < 4; ni++) {
                int row = ni * 16 + b_row_off;
                int unit = kvc * 2 + b_hi;
                uint32_t ro = (uint32_t)row * 128 + (uint32_t)((unit ^ (row & 7)) << 4);
                uint32_t vh4[4];
                ldsm4(vh4, st + A_BUF + ro);
#pragma unroll
                for (int hf = 0; hf < 2; hf++) {
                    float* op = o[ni * 2 + hf];
                    mma16816(op, ph4, &vh4[hf * 2]);
                    mma16816(op, pl4, &vh4[hf * 2]);
                }
            }
        }
        __syncthreads();
    }

    // ---- write ctx hi/lo --------------------------------------------------
    const int r = lane >> 2, cpair = (lane & 3) * 2;
    const int b = bh >> 4, h = bh & 15;
    float inv0 = 1.f / l0, inv1 = 1.f / l1;
    int row0 = q0 + w * 16 + r, row1 = row0 + 8;
#pragma unroll
    for (int j = 0; j < 8; j++) {
        int col = h * HD + j * 8 + cpair;
        float v00 = o[j][0] * inv0, v01 = o[j][1] * inv0;
        float v10 = o[j][2] * inv1, v11 = o[j][3] * inv1;
        uint32_t H0 = packh(v00, v01), L0 = packh(v00 - h_lo(H0), v01 - h_hi(H0));
        uint32_t H1 = packh(v10, v11), L1 = packh(v10 - h_lo(H1), v11 - h_hi(H1));
        size_t i0 = ((size_t)b * SS + row0) * DD + col;
        size_t i1 = ((size_t)b * SS + row1) * DD + col;
        *(uint32_t*)(g_ch + i0) = H0;  *(uint32_t*)(g_cl + i0) = L0;
        *(uint32_t*)(g_ch + i1) = H1;  *(uint32_t*)(g_cl + i1) = L1;
    }
}

// ---------------------------------------------------------------------------
extern "C" void kernel_launch(void* const* d_in, const int* in_sizes, int n_in,
                              void* d_out, int out_size)
{
    const float* x      = (const float*)d_in[0];
    const float* w_qkv  = (const float*)d_in[1];
    const float* b_qkv  = (const float*)d_in[2];
    const float* w_proj = (const float*)d_in[3];
    const float* b_proj = (const float*)d_in[4];
    float* out = (float*)d_out;

    cudaFuncSetAttribute(gemm_mma_f16x2,
                         cudaFuncAttributeMaxDynamicSharedMemorySize, G_SMEM);
    cudaFuncSetAttribute(attn_mma,
                         cudaFuncAttributeMaxDynamicSharedMemorySize, A_SMEM);

    int nx4 = BB*SS*DD/4;
    convert_split4<<<(nx4 + 255)/256, 256>>>((const float4*)x, nx4);
    convert_transpose<<<dim3(3*DD/32, DD/32), dim3(32, 8)>>>(w_qkv, DD, 3*DD, 0);
    convert_transpose<<<dim3(DD/32, DD/32), dim3(32, 8)>>>(w_proj, DD, DD, 1);

    gemm_mma_f16x2<<<dim3(3*DD/128, BB*SS/128), 256, G_SMEM>>>(b_qkv, 0, nullptr);

    attn_mma<<<dim3(SS/128, BB*HH), 256, A_SMEM>>>();

    gemm_mma_f16x2<<<dim3(DD/128, BB*SS/128), 256, G_SMEM>>>(b_proj, 1, out);
}